// round 1
// baseline (speedup 1.0000x reference)
#include <cuda_runtime.h>
#include <cuda_bf16.h>
#include <math.h>

// ============================================================================
// RegionAugmentedSelfAttention  (B=128, S=144, D=1024, GRID=12)
//
// Pipeline:
//   1. bias[i,j]  = relu( sum_d relu(dx*Wl0[d] + dy*Wl1[d] + bl[d]) * wg[i,d] )
//      (batch-independent -> computed ONCE, 144x144)
//   2. q = relu(query@Wq + bq), k = relu(key@Wk + bk), v = relu(value@Wv + bv)
//   3. attn = q @ k^T * D^-0.5 + bias
//   4. softmax rows
//   5. out = attn @ v
//
// Input order (metadata): query,key,value,Wq,bq,Wk,bk,Wv,bv,Wl,bl,w_g
// ============================================================================

#define B_  128
#define S_  144
#define D_  1024
#define BS_ (B_ * S_)          // 18432

// -------- scratch (static device globals: no runtime allocation) -----------
__device__ float g_q[BS_ * D_];
__device__ float g_k[BS_ * D_];
__device__ float g_v[BS_ * D_];
__device__ float g_attn[B_ * S_ * S_];
__device__ float g_bias[S_ * S_];

// ============================================================================
// Kernel 1: relative-position bias table (144 x 144)
// ============================================================================
__global__ void bias_kernel(const float* __restrict__ Wl,   // (4, D)
                            const float* __restrict__ bl,   // (D)
                            const float* __restrict__ wg,   // (S, D)
                            float* __restrict__ bias)       // (S, S)
{
    int i = blockIdx.y;   // query grid cell
    int j = blockIdx.x;   // key grid cell
    int ri = i / 12, ci = i % 12;
    int rj = j / 12, cj = j % 12;
    // w = h = 2 everywhere, dw = dh = 0
    float dx = logf(fmaxf(fabsf((float)(ri - rj)) * 0.5f, 1e-10f));
    float dy = logf(fmaxf(fabsf((float)(ci - cj)) * 0.5f, 1e-10f));

    float sum = 0.f;
    for (int d = threadIdx.x; d < D_; d += blockDim.x) {
        float r = fmaxf(fmaf(dx, Wl[d], fmaf(dy, Wl[D_ + d], bl[d])), 0.f);
        sum += r * wg[i * D_ + d];
    }
    // block reduce (256 threads = 8 warps)
    __shared__ float wsum[8];
    int lane = threadIdx.x & 31;
    int wid  = threadIdx.x >> 5;
    #pragma unroll
    for (int o = 16; o; o >>= 1) sum += __shfl_xor_sync(0xffffffffu, sum, o);
    if (lane == 0) wsum[wid] = sum;
    __syncthreads();
    if (threadIdx.x == 0) {
        float t = 0.f;
        #pragma unroll
        for (int w = 0; w < 8; w++) t += wsum[w];
        bias[i * S_ + j] = fmaxf(t, 0.f);
    }
}

// ============================================================================
// Kernel 2: fused projection GEMM  C = relu(A @ W + b)
//   A: (M=18432, K=1024) row-major, W: (K=1024, N=1024) row-major
//   128x128 tile, BK=8, 256 threads, 8x8 per thread
// ============================================================================
__global__ __launch_bounds__(256, 2)
void proj_gemm(const float* __restrict__ A, const float* __restrict__ W,
               const float* __restrict__ bias, float* __restrict__ C)
{
    const int K = D_, N = D_;
    __shared__ float As[8][128];
    __shared__ float Bs[8][128];

    int tid = threadIdx.x;
    int tx = tid & 15;            // 0..15 -> col group
    int ty = tid >> 4;            // 0..15 -> row group
    int rowBase = blockIdx.y * 128;
    int colBase = blockIdx.x * 128;

    int aRow = tid >> 1;          // 0..127
    int aCol = (tid & 1) * 4;     // 0 or 4
    int bRow = tid >> 5;          // 0..7
    int bCol = (tid & 31) * 4;    // 0..124

    const float* Aptr = A + (size_t)(rowBase + aRow) * K + aCol;
    const float* Wptr = W + (size_t)bRow * N + colBase + bCol;

    float acc[8][8];
    #pragma unroll
    for (int i = 0; i < 8; i++)
        #pragma unroll
        for (int j = 0; j < 8; j++) acc[i][j] = 0.f;

    for (int k0 = 0; k0 < K; k0 += 8) {
        float4 a = *(const float4*)(Aptr + k0);
        As[aCol + 0][aRow] = a.x;
        As[aCol + 1][aRow] = a.y;
        As[aCol + 2][aRow] = a.z;
        As[aCol + 3][aRow] = a.w;
        *(float4*)&Bs[bRow][bCol] = *(const float4*)(Wptr + (size_t)k0 * N);
        __syncthreads();

        #pragma unroll
        for (int kk = 0; kk < 8; kk++) {
            float ra[8], rb[8];
            *(float4*)&ra[0] = *(float4*)&As[kk][ty * 8];
            *(float4*)&ra[4] = *(float4*)&As[kk][ty * 8 + 4];
            *(float4*)&rb[0] = *(float4*)&Bs[kk][tx * 8];
            *(float4*)&rb[4] = *(float4*)&Bs[kk][tx * 8 + 4];
            #pragma unroll
            for (int i = 0; i < 8; i++)
                #pragma unroll
                for (int j = 0; j < 8; j++)
                    acc[i][j] = fmaf(ra[i], rb[j], acc[i][j]);
        }
        __syncthreads();
    }

    #pragma unroll
    for (int i = 0; i < 8; i++) {
        int r = rowBase + ty * 8 + i;
        #pragma unroll
        for (int j = 0; j < 8; j += 4) {
            int c = colBase + tx * 8 + j;
            float4 o;
            o.x = fmaxf(acc[i][j + 0] + bias[c + 0], 0.f);
            o.y = fmaxf(acc[i][j + 1] + bias[c + 1], 0.f);
            o.z = fmaxf(acc[i][j + 2] + bias[c + 2], 0.f);
            o.w = fmaxf(acc[i][j + 3] + bias[c + 3], 0.f);
            *(float4*)&C[(size_t)r * N + c] = o;
        }
    }
}

// ============================================================================
// Kernel 3: attention scores  attn[b,i,j] = (q_b @ k_b^T)[i,j]*scale + bias[i,j]
//   per block: 48x48 tile of one batch, BK=16, 256 threads, 3x3 per thread
// ============================================================================
__global__ __launch_bounds__(256)
void scores_kernel(const float* __restrict__ q, const float* __restrict__ k,
                   const float* __restrict__ bias, float* __restrict__ attn,
                   float scale)
{
    __shared__ float As[16][48];
    __shared__ float Bs[16][48];

    int tid = threadIdx.x;
    int tx = tid & 15, ty = tid >> 4;
    int b = blockIdx.z;
    int rowBase = blockIdx.y * 48;
    int colBase = blockIdx.x * 48;

    const float* qb = q + (size_t)b * S_ * D_;
    const float* kb = k + (size_t)b * S_ * D_;

    float acc[3][3] = {};

    for (int k0 = 0; k0 < D_; k0 += 16) {
        for (int idx = tid; idx < 48 * 16; idx += 256) {
            int r = idx >> 4, kk = idx & 15;
            As[kk][r] = qb[(size_t)(rowBase + r) * D_ + k0 + kk];
            Bs[kk][r] = kb[(size_t)(colBase + r) * D_ + k0 + kk];
        }
        __syncthreads();
        #pragma unroll
        for (int kk = 0; kk < 16; kk++) {
            float ra[3], rb[3];
            #pragma unroll
            for (int i = 0; i < 3; i++) ra[i] = As[kk][ty * 3 + i];
            #pragma unroll
            for (int j = 0; j < 3; j++) rb[j] = Bs[kk][tx * 3 + j];
            #pragma unroll
            for (int i = 0; i < 3; i++)
                #pragma unroll
                for (int j = 0; j < 3; j++)
                    acc[i][j] = fmaf(ra[i], rb[j], acc[i][j]);
        }
        __syncthreads();
    }

    #pragma unroll
    for (int i = 0; i < 3; i++) {
        int r = rowBase + ty * 3 + i;
        #pragma unroll
        for (int j = 0; j < 3; j++) {
            int c = colBase + tx * 3 + j;
            attn[((size_t)b * S_ + r) * S_ + c] =
                fmaf(acc[i][j], scale, bias[r * S_ + c]);
        }
    }
}

// ============================================================================
// Kernel 4: softmax over rows of attn (B*S rows, each 144 wide)
//   one warp per row, 8 warps per block
// ============================================================================
__global__ void softmax_kernel(float* __restrict__ attn)
{
    int warp = (blockIdx.x * blockDim.x + threadIdx.x) >> 5;
    int lane = threadIdx.x & 31;
    if (warp >= B_ * S_) return;
    float* row = attn + (size_t)warp * S_;

    float v[5];
    float mx = -INFINITY;
    #pragma unroll
    for (int i = 0; i < 5; i++) {
        int idx = lane + i * 32;
        v[i] = (idx < S_) ? row[idx] : -INFINITY;
        mx = fmaxf(mx, v[i]);
    }
    #pragma unroll
    for (int o = 16; o; o >>= 1) mx = fmaxf(mx, __shfl_xor_sync(0xffffffffu, mx, o));

    float s = 0.f;
    #pragma unroll
    for (int i = 0; i < 5; i++) {
        v[i] = __expf(v[i] - mx);   // expf(-inf)=0 handles tail lanes
        s += v[i];
    }
    #pragma unroll
    for (int o = 16; o; o >>= 1) s += __shfl_xor_sync(0xffffffffu, s, o);

    float inv = 1.f / s;
    #pragma unroll
    for (int i = 0; i < 5; i++) {
        int idx = lane + i * 32;
        if (idx < S_) row[idx] = v[i] * inv;
    }
}

// ============================================================================
// Kernel 5: out = attn @ v   (per batch: 144x1024, K=144)
//   tile 48x64, BK=16, 256 threads, 3x4 per thread
// ============================================================================
__global__ __launch_bounds__(256)
void av_kernel(const float* __restrict__ attn, const float* __restrict__ v,
               float* __restrict__ out)
{
    __shared__ float As[16][48];
    __shared__ float Bs[16][64];

    int tid = threadIdx.x;
    int tx = tid & 15, ty = tid >> 4;
    int b = blockIdx.z;
    int rowBase = blockIdx.y * 48;
    int colBase = blockIdx.x * 64;

    const float* ab = attn + (size_t)b * S_ * S_;
    const float* vb = v + (size_t)b * S_ * D_;

    int bR = tid >> 4;            // 0..15 (k within tile)
    int bC = (tid & 15) * 4;      // 0..60

    float acc[3][4] = {};

    for (int k0 = 0; k0 < S_; k0 += 16) {
        for (int idx = tid; idx < 48 * 16; idx += 256) {
            int r = idx >> 4, kk = idx & 15;
            As[kk][r] = ab[(size_t)(rowBase + r) * S_ + k0 + kk];
        }
        *(float4*)&Bs[bR][bC] =
            *(const float4*)&vb[(size_t)(k0 + bR) * D_ + colBase + bC];
        __syncthreads();
        #pragma unroll
        for (int kk = 0; kk < 16; kk++) {
            float ra[3], rb[4];
            #pragma unroll
            for (int i = 0; i < 3; i++) ra[i] = As[kk][ty * 3 + i];
            *(float4*)&rb[0] = *(float4*)&Bs[kk][tx * 4];
            #pragma unroll
            for (int i = 0; i < 3; i++)
                #pragma unroll
                for (int j = 0; j < 4; j++)
                    acc[i][j] = fmaf(ra[i], rb[j], acc[i][j]);
        }
        __syncthreads();
    }

    #pragma unroll
    for (int i = 0; i < 3; i++) {
        int r = rowBase + ty * 3 + i;
        float4 o = { acc[i][0], acc[i][1], acc[i][2], acc[i][3] };
        *(float4*)&out[((size_t)b * S_ + r) * D_ + colBase + tx * 4] = o;
    }
}

// ============================================================================
// launch
// ============================================================================
extern "C" void kernel_launch(void* const* d_in, const int* in_sizes, int n_in,
                              void* d_out, int out_size)
{
    const float* query = (const float*)d_in[0];
    const float* key   = (const float*)d_in[1];
    const float* value = (const float*)d_in[2];
    const float* Wq    = (const float*)d_in[3];
    const float* bq    = (const float*)d_in[4];
    const float* Wk    = (const float*)d_in[5];
    const float* bk    = (const float*)d_in[6];
    const float* Wv    = (const float*)d_in[7];
    const float* bv    = (const float*)d_in[8];
    const float* Wl    = (const float*)d_in[9];
    const float* bl    = (const float*)d_in[10];
    const float* wg    = (const float*)d_in[11];
    float* out = (float*)d_out;

    float* q;    cudaGetSymbolAddress((void**)&q,    g_q);
    float* k;    cudaGetSymbolAddress((void**)&k,    g_k);
    float* v;    cudaGetSymbolAddress((void**)&v,    g_v);
    float* attn; cudaGetSymbolAddress((void**)&attn, g_attn);
    float* bias; cudaGetSymbolAddress((void**)&bias, g_bias);

    // 1. relative-position bias table (batch-independent)
    bias_kernel<<<dim3(S_, S_), 256>>>(Wl, bl, wg, bias);

    // 2. projections
    dim3 pg(D_ / 128, BS_ / 128);     // (8, 144)
    proj_gemm<<<pg, 256>>>(query, Wq, bq, q);
    proj_gemm<<<pg, 256>>>(key,   Wk, bk, k);
    proj_gemm<<<pg, 256>>>(value, Wv, bv, v);

    // 3. scores (+ scale + bias)
    float scale = 1.0f / sqrtf((float)D_);
    scores_kernel<<<dim3(3, 3, B_), 256>>>(q, k, bias, attn, scale);

    // 4. softmax
    int rows = B_ * S_;
    softmax_kernel<<<(rows * 32 + 255) / 256, 256>>>(attn);

    // 5. out = attn @ v
    av_kernel<<<dim3(D_ / 64, 3, B_), 256>>>(attn, v, out);
}

// round 2
// speedup vs baseline: 2.1631x; 2.1631x over previous
#include <cuda_runtime.h>
#include <cuda_bf16.h>
#include <math.h>
#include <stdint.h>

// ============================================================================
// RegionAugmentedSelfAttention  (B=128, S=144, D=1024, GRID=12)
//   R2: projections moved to tf32 tensor cores (mma.sync.m16n8k8)
// ============================================================================

#define B_  128
#define S_  144
#define D_  1024
#define BS_ (B_ * S_)          // 18432

// -------- scratch (static device globals: no runtime allocation) -----------
__device__ float g_q[BS_ * D_];
__device__ float g_k[BS_ * D_];
__device__ float g_v[BS_ * D_];
__device__ float g_attn[B_ * S_ * S_];
__device__ float g_bias[S_ * S_];

// ============================================================================
// Kernel 1: relative-position bias table (144 x 144)
// ============================================================================
__global__ void bias_kernel(const float* __restrict__ Wl,   // (4, D)
                            const float* __restrict__ bl,   // (D)
                            const float* __restrict__ wg,   // (S, D)
                            float* __restrict__ bias)       // (S, S)
{
    int i = blockIdx.y;
    int j = blockIdx.x;
    int ri = i / 12, ci = i % 12;
    int rj = j / 12, cj = j % 12;
    float dx = logf(fmaxf(fabsf((float)(ri - rj)) * 0.5f, 1e-10f));
    float dy = logf(fmaxf(fabsf((float)(ci - cj)) * 0.5f, 1e-10f));

    float sum = 0.f;
    for (int d = threadIdx.x; d < D_; d += blockDim.x) {
        float r = fmaxf(fmaf(dx, Wl[d], fmaf(dy, Wl[D_ + d], bl[d])), 0.f);
        sum += r * wg[i * D_ + d];
    }
    __shared__ float wsum[8];
    int lane = threadIdx.x & 31;
    int wid  = threadIdx.x >> 5;
    #pragma unroll
    for (int o = 16; o; o >>= 1) sum += __shfl_xor_sync(0xffffffffu, sum, o);
    if (lane == 0) wsum[wid] = sum;
    __syncthreads();
    if (threadIdx.x == 0) {
        float t = 0.f;
        #pragma unroll
        for (int w = 0; w < 8; w++) t += wsum[w];
        bias[i * S_ + j] = fmaxf(t, 0.f);
    }
}

// ============================================================================
// Kernel 2: fused projection GEMM  C = relu(A @ W + b)   -- tf32 tensor cores
//   A: (M=18432, K=1024) rm,  W: (K=1024, N=1024) rm
//   CTA tile 128x128, BK=32, 256 threads (8 warps @ 64x32 each)
//   mma.sync.aligned.m16n8k8.row.col.f32.tf32.tf32.f32
// ============================================================================
#define PBM 128
#define PBN 128
#define PBK 32
#define AS_STRIDE 36     // 32 + 4 pad  -> A-frag banks (4g+t)%32 bijective
#define BS_STRIDE 136    // 128 + 8 pad -> B-frag banks (8t+g)%32 bijective
#define AS_WORDS (PBM * AS_STRIDE)    // 4608
#define BS_WORDS (PBK * BS_STRIDE)    // 4352
#define PROJ_SMEM ((AS_WORDS + BS_WORDS) * 2 * 4)  // 71680 bytes

__device__ __forceinline__ uint32_t f2tf32(float f) {
    uint32_t u;
    asm("cvt.rna.tf32.f32 %0, %1;" : "=r"(u) : "f"(f));
    return u;
}

__device__ __forceinline__ void mma_tf32(float (&d)[4],
                                         const uint32_t (&a)[4],
                                         const uint32_t (&b)[2]) {
    asm volatile(
        "mma.sync.aligned.m16n8k8.row.col.f32.tf32.tf32.f32 "
        "{%0,%1,%2,%3}, {%4,%5,%6,%7}, {%8,%9}, {%0,%1,%2,%3};\n"
        : "+f"(d[0]), "+f"(d[1]), "+f"(d[2]), "+f"(d[3])
        : "r"(a[0]), "r"(a[1]), "r"(a[2]), "r"(a[3]),
          "r"(b[0]), "r"(b[1]));
}

__global__ __launch_bounds__(256, 1)
void proj_gemm_tc(const float* __restrict__ A, const float* __restrict__ W,
                  const float* __restrict__ bvec, float* __restrict__ C)
{
    extern __shared__ uint32_t smem[];
    uint32_t* As = smem;                       // [2][PBM][AS_STRIDE]
    uint32_t* Bs = smem + 2 * AS_WORDS;        // [2][PBK][BS_STRIDE]

    const int K = D_, N = D_;
    const int tid  = threadIdx.x;
    const int lane = tid & 31;
    const int warp = tid >> 5;
    const int g = lane >> 2;      // groupID 0..7
    const int t = lane & 3;       // threadID in group 0..3

    const int rowBase = blockIdx.y * PBM;
    const int colBase = blockIdx.x * PBN;
    const int warpRow = (warp >> 2) * 64;      // 0 or 64
    const int warpCol = (warp & 3) * 32;       // 0,32,64,96

    // ---- global load indexing (per thread: 4 float4 from A, 4 from B) ----
    // A tile: 128 rows x 32 cols = 1024 float4 (8 per row)
    // B tile:  32 rows x 128 cols = 1024 float4 (32 per row)
    const int aRow0 = tid >> 3;            // +32 per i
    const int aCol  = (tid & 7) * 4;
    const int bRow0 = tid >> 5;            // +8 per i
    const int bCol  = (tid & 31) * 4;

    const float* Ag = A + (size_t)(rowBase + aRow0) * K + aCol;
    const float* Bg = W + (size_t)bRow0 * N + colBase + bCol;

    float acc[4][4][4];
    #pragma unroll
    for (int i = 0; i < 4; i++)
        #pragma unroll
        for (int j = 0; j < 4; j++)
            #pragma unroll
            for (int r = 0; r < 4; r++) acc[i][j][r] = 0.f;

    float4 rA[4], rB[4];

    // ---- prologue: load k-tile 0 ----
    #pragma unroll
    for (int i = 0; i < 4; i++) {
        rA[i] = *(const float4*)(Ag + (size_t)(i * 32) * K);
        rB[i] = *(const float4*)(Bg + (size_t)(i * 8) * N);
    }
    #pragma unroll
    for (int i = 0; i < 4; i++) {
        uint4 ua = { f2tf32(rA[i].x), f2tf32(rA[i].y), f2tf32(rA[i].z), f2tf32(rA[i].w) };
        *(uint4*)&As[(aRow0 + i * 32) * AS_STRIDE + aCol] = ua;
        uint4 ub = { f2tf32(rB[i].x), f2tf32(rB[i].y), f2tf32(rB[i].z), f2tf32(rB[i].w) };
        *(uint4*)&Bs[(bRow0 + i * 8) * BS_STRIDE + bCol] = ub;
    }
    __syncthreads();

    const int NKT = K / PBK;   // 32
    for (int kt = 0; kt < NKT; kt++) {
        int cur = kt & 1, nxt = cur ^ 1;

        // prefetch next k-tile from global
        if (kt + 1 < NKT) {
            const float* Ag2 = Ag + (size_t)(kt + 1) * PBK;
            const float* Bg2 = Bg + (size_t)(kt + 1) * PBK * N;
            #pragma unroll
            for (int i = 0; i < 4; i++) {
                rA[i] = *(const float4*)(Ag2 + (size_t)(i * 32) * K);
                rB[i] = *(const float4*)(Bg2 + (size_t)(i * 8) * N);
            }
        }

        // compute current tile: 4 k-steps of 8
        const uint32_t* Ac = As + cur * AS_WORDS;
        const uint32_t* Bc = Bs + cur * BS_WORDS;
        #pragma unroll
        for (int ks = 0; ks < 4; ks++) {
            int kk = ks * 8;
            uint32_t af[4][4], bf[4][2];
            #pragma unroll
            for (int mt = 0; mt < 4; mt++) {
                int m0 = warpRow + mt * 16;
                af[mt][0] = Ac[(m0 + g)     * AS_STRIDE + kk + t];
                af[mt][1] = Ac[(m0 + g + 8) * AS_STRIDE + kk + t];
                af[mt][2] = Ac[(m0 + g)     * AS_STRIDE + kk + t + 4];
                af[mt][3] = Ac[(m0 + g + 8) * AS_STRIDE + kk + t + 4];
            }
            #pragma unroll
            for (int nt = 0; nt < 4; nt++) {
                int n0 = warpCol + nt * 8;
                bf[nt][0] = Bc[(kk + t)     * BS_STRIDE + n0 + g];
                bf[nt][1] = Bc[(kk + t + 4) * BS_STRIDE + n0 + g];
            }
            #pragma unroll
            for (int mt = 0; mt < 4; mt++)
                #pragma unroll
                for (int nt = 0; nt < 4; nt++)
                    mma_tf32(acc[mt][nt], af[mt], bf[nt]);
        }

        // stage next tile into the other smem buffer
        if (kt + 1 < NKT) {
            uint32_t* An = As + nxt * AS_WORDS;
            uint32_t* Bn = Bs + nxt * BS_WORDS;
            #pragma unroll
            for (int i = 0; i < 4; i++) {
                uint4 ua = { f2tf32(rA[i].x), f2tf32(rA[i].y), f2tf32(rA[i].z), f2tf32(rA[i].w) };
                *(uint4*)&An[(aRow0 + i * 32) * AS_STRIDE + aCol] = ua;
                uint4 ub = { f2tf32(rB[i].x), f2tf32(rB[i].y), f2tf32(rB[i].z), f2tf32(rB[i].w) };
                *(uint4*)&Bn[(bRow0 + i * 8) * BS_STRIDE + bCol] = ub;
            }
            __syncthreads();
        }
    }

    // ---- epilogue: bias + relu, float2 stores ----
    #pragma unroll
    for (int mt = 0; mt < 4; mt++) {
        int r0 = rowBase + warpRow + mt * 16 + g;
        #pragma unroll
        for (int nt = 0; nt < 4; nt++) {
            int c = colBase + warpCol + nt * 8 + 2 * t;
            float b0 = bvec[c], b1 = bvec[c + 1];
            float2 o0 = { fmaxf(acc[mt][nt][0] + b0, 0.f),
                          fmaxf(acc[mt][nt][1] + b1, 0.f) };
            float2 o1 = { fmaxf(acc[mt][nt][2] + b0, 0.f),
                          fmaxf(acc[mt][nt][3] + b1, 0.f) };
            *(float2*)&C[(size_t)r0 * N + c]       = o0;
            *(float2*)&C[(size_t)(r0 + 8) * N + c] = o1;
        }
    }
}

// ============================================================================
// Kernel 3: attention scores  attn[b,i,j] = (q_b @ k_b^T)[i,j]*scale + bias[i,j]
// ============================================================================
__global__ __launch_bounds__(256)
void scores_kernel(const float* __restrict__ q, const float* __restrict__ k,
                   const float* __restrict__ bias, float* __restrict__ attn,
                   float scale)
{
    __shared__ float As[16][48];
    __shared__ float Bs[16][48];

    int tid = threadIdx.x;
    int tx = tid & 15, ty = tid >> 4;
    int b = blockIdx.z;
    int rowBase = blockIdx.y * 48;
    int colBase = blockIdx.x * 48;

    const float* qb = q + (size_t)b * S_ * D_;
    const float* kb = k + (size_t)b * S_ * D_;

    float acc[3][3] = {};

    for (int k0 = 0; k0 < D_; k0 += 16) {
        for (int idx = tid; idx < 48 * 16; idx += 256) {
            int r = idx >> 4, kk = idx & 15;
            As[kk][r] = qb[(size_t)(rowBase + r) * D_ + k0 + kk];
            Bs[kk][r] = kb[(size_t)(colBase + r) * D_ + k0 + kk];
        }
        __syncthreads();
        #pragma unroll
        for (int kk = 0; kk < 16; kk++) {
            float ra[3], rb[3];
            #pragma unroll
            for (int i = 0; i < 3; i++) ra[i] = As[kk][ty * 3 + i];
            #pragma unroll
            for (int j = 0; j < 3; j++) rb[j] = Bs[kk][tx * 3 + j];
            #pragma unroll
            for (int i = 0; i < 3; i++)
                #pragma unroll
                for (int j = 0; j < 3; j++)
                    acc[i][j] = fmaf(ra[i], rb[j], acc[i][j]);
        }
        __syncthreads();
    }

    #pragma unroll
    for (int i = 0; i < 3; i++) {
        int r = rowBase + ty * 3 + i;
        #pragma unroll
        for (int j = 0; j < 3; j++) {
            int c = colBase + tx * 3 + j;
            attn[((size_t)b * S_ + r) * S_ + c] =
                fmaf(acc[i][j], scale, bias[r * S_ + c]);
        }
    }
}

// ============================================================================
// Kernel 4: softmax over rows of attn
// ============================================================================
__global__ void softmax_kernel(float* __restrict__ attn)
{
    int warp = (blockIdx.x * blockDim.x + threadIdx.x) >> 5;
    int lane = threadIdx.x & 31;
    if (warp >= B_ * S_) return;
    float* row = attn + (size_t)warp * S_;

    float v[5];
    float mx = -INFINITY;
    #pragma unroll
    for (int i = 0; i < 5; i++) {
        int idx = lane + i * 32;
        v[i] = (idx < S_) ? row[idx] : -INFINITY;
        mx = fmaxf(mx, v[i]);
    }
    #pragma unroll
    for (int o = 16; o; o >>= 1) mx = fmaxf(mx, __shfl_xor_sync(0xffffffffu, mx, o));

    float s = 0.f;
    #pragma unroll
    for (int i = 0; i < 5; i++) {
        v[i] = __expf(v[i] - mx);
        s += v[i];
    }
    #pragma unroll
    for (int o = 16; o; o >>= 1) s += __shfl_xor_sync(0xffffffffu, s, o);

    float inv = 1.f / s;
    #pragma unroll
    for (int i = 0; i < 5; i++) {
        int idx = lane + i * 32;
        if (idx < S_) row[idx] = v[i] * inv;
    }
}

// ============================================================================
// Kernel 5: out = attn @ v
// ============================================================================
__global__ __launch_bounds__(256)
void av_kernel(const float* __restrict__ attn, const float* __restrict__ v,
               float* __restrict__ out)
{
    __shared__ float As[16][48];
    __shared__ float Bs[16][64];

    int tid = threadIdx.x;
    int tx = tid & 15, ty = tid >> 4;
    int b = blockIdx.z;
    int rowBase = blockIdx.y * 48;
    int colBase = blockIdx.x * 64;

    const float* ab = attn + (size_t)b * S_ * S_;
    const float* vb = v + (size_t)b * S_ * D_;

    int bR = tid >> 4;
    int bC = (tid & 15) * 4;

    float acc[3][4] = {};

    for (int k0 = 0; k0 < S_; k0 += 16) {
        for (int idx = tid; idx < 48 * 16; idx += 256) {
            int r = idx >> 4, kk = idx & 15;
            As[kk][r] = ab[(size_t)(rowBase + r) * S_ + k0 + kk];
        }
        *(float4*)&Bs[bR][bC] =
            *(const float4*)&vb[(size_t)(k0 + bR) * D_ + colBase + bC];
        __syncthreads();
        #pragma unroll
        for (int kk = 0; kk < 16; kk++) {
            float ra[3], rb[4];
            #pragma unroll
            for (int i = 0; i < 3; i++) ra[i] = As[kk][ty * 3 + i];
            *(float4*)&rb[0] = *(float4*)&Bs[kk][tx * 4];
            #pragma unroll
            for (int i = 0; i < 3; i++)
                #pragma unroll
                for (int j = 0; j < 4; j++)
                    acc[i][j] = fmaf(ra[i], rb[j], acc[i][j]);
        }
        __syncthreads();
    }

    #pragma unroll
    for (int i = 0; i < 3; i++) {
        int r = rowBase + ty * 3 + i;
        float4 o = { acc[i][0], acc[i][1], acc[i][2], acc[i][3] };
        *(float4*)&out[((size_t)b * S_ + r) * D_ + colBase + tx * 4] = o;
    }
}

// ============================================================================
// launch
// ============================================================================
extern "C" void kernel_launch(void* const* d_in, const int* in_sizes, int n_in,
                              void* d_out, int out_size)
{
    const float* query = (const float*)d_in[0];
    const float* key   = (const float*)d_in[1];
    const float* value = (const float*)d_in[2];
    const float* Wq    = (const float*)d_in[3];
    const float* bq    = (const float*)d_in[4];
    const float* Wk    = (const float*)d_in[5];
    const float* bk    = (const float*)d_in[6];
    const float* Wv    = (const float*)d_in[7];
    const float* bv    = (const float*)d_in[8];
    const float* Wl    = (const float*)d_in[9];
    const float* bl    = (const float*)d_in[10];
    const float* wg    = (const float*)d_in[11];
    float* out = (float*)d_out;

    float* q;    cudaGetSymbolAddress((void**)&q,    g_q);
    float* k;    cudaGetSymbolAddress((void**)&k,    g_k);
    float* v;    cudaGetSymbolAddress((void**)&v,    g_v);
    float* attn; cudaGetSymbolAddress((void**)&attn, g_attn);
    float* bias; cudaGetSymbolAddress((void**)&bias, g_bias);

    static bool attr_set = false;
    if (!attr_set) {
        cudaFuncSetAttribute(proj_gemm_tc,
                             cudaFuncAttributeMaxDynamicSharedMemorySize,
                             PROJ_SMEM);
        attr_set = true;
    }

    // 1. relative-position bias table (batch-independent)
    bias_kernel<<<dim3(S_, S_), 256>>>(Wl, bl, wg, bias);

    // 2. projections (tf32 tensor cores)
    dim3 pg(D_ / PBN, BS_ / PBM);     // (8, 144)
    proj_gemm_tc<<<pg, 256, PROJ_SMEM>>>(query, Wq, bq, q);
    proj_gemm_tc<<<pg, 256, PROJ_SMEM>>>(key,   Wk, bk, k);
    proj_gemm_tc<<<pg, 256, PROJ_SMEM>>>(value, Wv, bv, v);

    // 3. scores (+ scale + bias)
    float scale = 1.0f / sqrtf((float)D_);
    scores_kernel<<<dim3(3, 3, B_), 256>>>(q, k, bias, attn, scale);

    // 4. softmax
    int rows = B_ * S_;
    softmax_kernel<<<(rows * 32 + 255) / 256, 256>>>(attn);

    // 5. out = attn @ v
    av_kernel<<<dim3(D_ / 64, 3, B_), 256>>>(attn, v, out);
}

// round 3
// speedup vs baseline: 3.6966x; 1.7089x over previous
#include <cuda_runtime.h>
#include <cuda_bf16.h>
#include <math.h>
#include <stdint.h>

// ============================================================================
// RegionAugmentedSelfAttention  (B=128, S=144, D=1024, GRID=12)
//   R3: cp.async 2-stage pipelines, 2 CTA/SM projections, tf32 tensor cores
//       for scores and attn@v as well.
// ============================================================================

#define B_  128
#define S_  144
#define D_  1024
#define BS_ (B_ * S_)          // 18432

// -------- scratch (static device globals: no runtime allocation) -----------
__device__ float g_q[BS_ * D_];
__device__ float g_k[BS_ * D_];
__device__ float g_v[BS_ * D_];
__device__ float g_attn[B_ * S_ * S_];
__device__ float g_bias[S_ * S_];

// ---------------------------------------------------------------------------
// PTX helpers
// ---------------------------------------------------------------------------
__device__ __forceinline__ uint32_t f2tf32(float f) {
    uint32_t u;
    asm("cvt.rna.tf32.f32 %0, %1;" : "=r"(u) : "f"(f));
    return u;
}

__device__ __forceinline__ void mma_tf32(float (&d)[4],
                                         const uint32_t (&a)[4],
                                         const uint32_t (&b)[2]) {
    asm volatile(
        "mma.sync.aligned.m16n8k8.row.col.f32.tf32.tf32.f32 "
        "{%0,%1,%2,%3}, {%4,%5,%6,%7}, {%8,%9}, {%0,%1,%2,%3};\n"
        : "+f"(d[0]), "+f"(d[1]), "+f"(d[2]), "+f"(d[3])
        : "r"(a[0]), "r"(a[1]), "r"(a[2]), "r"(a[3]),
          "r"(b[0]), "r"(b[1]));
}

__device__ __forceinline__ void cp_async16(uint32_t smem_addr, const void* gptr) {
    asm volatile("cp.async.cg.shared.global [%0], [%1], 16;\n"
                 :: "r"(smem_addr), "l"(gptr));
}
#define CP_COMMIT()  asm volatile("cp.async.commit_group;\n")
#define CP_WAIT(N)   asm volatile("cp.async.wait_group %0;\n" :: "n"(N))

// ============================================================================
// Kernel 1: relative-position bias table (144 x 144)
// ============================================================================
__global__ void bias_kernel(const float* __restrict__ Wl,   // (4, D)
                            const float* __restrict__ bl,   // (D)
                            const float* __restrict__ wg,   // (S, D)
                            float* __restrict__ bias)       // (S, S)
{
    int i = blockIdx.y;
    int j = blockIdx.x;
    int ri = i / 12, ci = i % 12;
    int rj = j / 12, cj = j % 12;
    float dx = logf(fmaxf(fabsf((float)(ri - rj)) * 0.5f, 1e-10f));
    float dy = logf(fmaxf(fabsf((float)(ci - cj)) * 0.5f, 1e-10f));

    float sum = 0.f;
    for (int d = threadIdx.x; d < D_; d += blockDim.x) {
        float r = fmaxf(fmaf(dx, Wl[d], fmaf(dy, Wl[D_ + d], bl[d])), 0.f);
        sum += r * wg[i * D_ + d];
    }
    __shared__ float wsum[8];
    int lane = threadIdx.x & 31;
    int wid  = threadIdx.x >> 5;
    #pragma unroll
    for (int o = 16; o; o >>= 1) sum += __shfl_xor_sync(0xffffffffu, sum, o);
    if (lane == 0) wsum[wid] = sum;
    __syncthreads();
    if (threadIdx.x == 0) {
        float t = 0.f;
        #pragma unroll
        for (int w = 0; w < 8; w++) t += wsum[w];
        bias[i * S_ + j] = fmaxf(t, 0.f);
    }
}

// ============================================================================
// Kernel 2: fused projection GEMM  C = relu(A @ W + b)   -- tf32 tensor cores
//   gridDim.z in {0,1,2} selects (query,Wq,bq,q) / (key,...) / (value,...)
//   CTA tile 128x128, BK=32, 2-stage cp.async, 256 threads (8 warps @ 64x32)
// ============================================================================
#define PBM 128
#define PBN 128
#define PBK 32
#define PAS 36                              // A smem stride (words)
#define PBS 136                             // B smem stride (words)
#define P_AW (PBM * PAS)                    // A stage words: 4608
#define P_BW (PBK * PBS)                    // B stage words: 4352
#define PROJ_SMEM ((P_AW + P_BW) * 2 * 4)   // 71680 bytes

__global__ __launch_bounds__(256, 2)
void proj_gemm_tc(const float* __restrict__ Aq, const float* __restrict__ Ak,
                  const float* __restrict__ Av,
                  const float* __restrict__ Wq, const float* __restrict__ Wk,
                  const float* __restrict__ Wv,
                  const float* __restrict__ bq, const float* __restrict__ bk,
                  const float* __restrict__ bv,
                  float* __restrict__ Cq, float* __restrict__ Ck,
                  float* __restrict__ Cv)
{
    const float *A, *W, *bvec;
    float *C;
    if (blockIdx.z == 0)      { A = Aq; W = Wq; bvec = bq; C = Cq; }
    else if (blockIdx.z == 1) { A = Ak; W = Wk; bvec = bk; C = Ck; }
    else                      { A = Av; W = Wv; bvec = bv; C = Cv; }

    extern __shared__ float sm[];
    float* As = sm;                 // [2][128][36]
    float* Bs = sm + 2 * P_AW;      // [2][32][136]

    const int K = D_, N = D_;
    const int tid  = threadIdx.x;
    const int lane = tid & 31;
    const int warp = tid >> 5;
    const int g = lane >> 2;
    const int t = lane & 3;

    const int rowBase = blockIdx.y * PBM;
    const int colBase = blockIdx.x * PBN;
    const int warpRow = (warp >> 2) * 64;
    const int warpCol = (warp & 3) * 32;

    // loader indexing (4x 16B per operand per thread)
    const int aRow0 = tid >> 3;            // 0..31, +32 per i
    const int aCol  = (tid & 7) * 4;
    const int bRow0 = tid >> 5;            // 0..7, +8 per i
    const int bCol  = (tid & 31) * 4;

    const float* Ag = A + (size_t)(rowBase + aRow0) * K + aCol;
    const float* Bg = W + (size_t)bRow0 * N + colBase + bCol;

    uint32_t smem_u = (uint32_t)__cvta_generic_to_shared(sm);
    uint32_t aS = smem_u + (uint32_t)((aRow0 * PAS + aCol) * 4);
    uint32_t bS = smem_u + (uint32_t)((2 * P_AW + bRow0 * PBS + bCol) * 4);

    float acc[4][4][4];
    #pragma unroll
    for (int i = 0; i < 4; i++)
        #pragma unroll
        for (int j = 0; j < 4; j++)
            #pragma unroll
            for (int r = 0; r < 4; r++) acc[i][j][r] = 0.f;

    const int NKT = K / PBK;   // 32

    // prologue: stage 0
    #pragma unroll
    for (int i = 0; i < 4; i++) {
        cp_async16(aS + i * (32 * PAS * 4), Ag + (size_t)(i * 32) * K);
        cp_async16(bS + i * (8 * PBS * 4),  Bg + (size_t)(i * 8) * N);
    }
    CP_COMMIT();

    for (int kt = 0; kt < NKT; kt++) {
        int cur = kt & 1;
        if (kt + 1 < NKT) {
            int nxt = (kt + 1) & 1;
            const float* Ag2 = Ag + (size_t)(kt + 1) * PBK;
            const float* Bg2 = Bg + (size_t)(kt + 1) * PBK * N;
            #pragma unroll
            for (int i = 0; i < 4; i++) {
                cp_async16(aS + (uint32_t)(nxt * P_AW * 4) + i * (32 * PAS * 4),
                           Ag2 + (size_t)(i * 32) * K);
                cp_async16(bS + (uint32_t)(nxt * P_BW * 4) + i * (8 * PBS * 4),
                           Bg2 + (size_t)(i * 8) * N);
            }
            CP_COMMIT();
            CP_WAIT(1);
        } else {
            CP_WAIT(0);
        }
        __syncthreads();

        const float* Ac = As + cur * P_AW;
        const float* Bc = Bs + cur * P_BW;
        #pragma unroll
        for (int ks = 0; ks < 4; ks++) {
            int kk = ks * 8;
            uint32_t af[4][4], bf[4][2];
            #pragma unroll
            for (int mt = 0; mt < 4; mt++) {
                int m0 = warpRow + mt * 16;
                af[mt][0] = f2tf32(Ac[(m0 + g)     * PAS + kk + t]);
                af[mt][1] = f2tf32(Ac[(m0 + g + 8) * PAS + kk + t]);
                af[mt][2] = f2tf32(Ac[(m0 + g)     * PAS + kk + t + 4]);
                af[mt][3] = f2tf32(Ac[(m0 + g + 8) * PAS + kk + t + 4]);
            }
            #pragma unroll
            for (int nt = 0; nt < 4; nt++) {
                int n0 = warpCol + nt * 8;
                bf[nt][0] = f2tf32(Bc[(kk + t)     * PBS + n0 + g]);
                bf[nt][1] = f2tf32(Bc[(kk + t + 4) * PBS + n0 + g]);
            }
            #pragma unroll
            for (int mt = 0; mt < 4; mt++)
                #pragma unroll
                for (int nt = 0; nt < 4; nt++)
                    mma_tf32(acc[mt][nt], af[mt], bf[nt]);
        }
        __syncthreads();
    }

    // epilogue: bias + relu
    #pragma unroll
    for (int mt = 0; mt < 4; mt++) {
        int r0 = rowBase + warpRow + mt * 16 + g;
        #pragma unroll
        for (int nt = 0; nt < 4; nt++) {
            int c = colBase + warpCol + nt * 8 + 2 * t;
            float b0 = bvec[c], b1 = bvec[c + 1];
            float2 o0 = { fmaxf(acc[mt][nt][0] + b0, 0.f),
                          fmaxf(acc[mt][nt][1] + b1, 0.f) };
            float2 o1 = { fmaxf(acc[mt][nt][2] + b0, 0.f),
                          fmaxf(acc[mt][nt][3] + b1, 0.f) };
            *(float2*)&C[(size_t)r0 * N + c]       = o0;
            *(float2*)&C[(size_t)(r0 + 8) * N + c] = o1;
        }
    }
}

// ============================================================================
// Kernel 3: scores  attn[b] = q_b @ k_b^T * scale + bias   -- tf32 MMA
//   One CTA per batch. CTA tile 144x144, 9 warps (3x3 @ 48x48), BK=32,
//   2-stage cp.async over D.
// ============================================================================
#define SAS 36
#define S_TW (S_ * SAS)                     // 5184 words per tensor stage
#define SCORES_SMEM (S_TW * 4 * 4)          // 2 tensors x 2 stages: 82944 B

__global__ __launch_bounds__(288, 1)
void scores_tc(const float* __restrict__ q, const float* __restrict__ k,
               const float* __restrict__ bias, float* __restrict__ attn,
               float scale)
{
    extern __shared__ float sm[];
    float* Qs = sm;                 // [2][144][36]
    float* Ks = sm + 2 * S_TW;      // [2][144][36]

    const int b = blockIdx.x;
    const float* qb = q + (size_t)b * S_ * D_;
    const float* kb = k + (size_t)b * S_ * D_;

    const int tid  = threadIdx.x;
    const int lane = tid & 31;
    const int warp = tid >> 5;                 // 0..8
    const int g = lane >> 2;
    const int t = lane & 3;
    const int warpRow = (warp / 3) * 48;
    const int warpCol = (warp % 3) * 48;

    // loaders: 144 rows x 8 chunks = 1152 chunks per tensor; 288 thr -> 4 each
    const int r0 = tid >> 3;                   // 0..35, +36 per i
    const int c0 = (tid & 7) * 4;

    uint32_t smem_u = (uint32_t)__cvta_generic_to_shared(sm);
    uint32_t qS = smem_u + (uint32_t)((r0 * SAS + c0) * 4);
    uint32_t kS = smem_u + (uint32_t)((2 * S_TW + r0 * SAS + c0) * 4);
    const float* qg = qb + (size_t)r0 * D_ + c0;
    const float* kg = kb + (size_t)r0 * D_ + c0;

    float acc[3][6][4];
    #pragma unroll
    for (int i = 0; i < 3; i++)
        #pragma unroll
        for (int j = 0; j < 6; j++)
            #pragma unroll
            for (int r = 0; r < 4; r++) acc[i][j][r] = 0.f;

    const int NKT = D_ / 32;   // 32

    #pragma unroll
    for (int i = 0; i < 4; i++) {
        cp_async16(qS + i * (36 * SAS * 4), qg + (size_t)(i * 36) * D_);
        cp_async16(kS + i * (36 * SAS * 4), kg + (size_t)(i * 36) * D_);
    }
    CP_COMMIT();

    for (int kt = 0; kt < NKT; kt++) {
        int cur = kt & 1;
        if (kt + 1 < NKT) {
            int nxt = (kt + 1) & 1;
            const float* qg2 = qg + (size_t)(kt + 1) * 32;
            const float* kg2 = kg + (size_t)(kt + 1) * 32;
            #pragma unroll
            for (int i = 0; i < 4; i++) {
                cp_async16(qS + (uint32_t)(nxt * S_TW * 4) + i * (36 * SAS * 4),
                           qg2 + (size_t)(i * 36) * D_);
                cp_async16(kS + (uint32_t)(nxt * S_TW * 4) + i * (36 * SAS * 4),
                           kg2 + (size_t)(i * 36) * D_);
            }
            CP_COMMIT();
            CP_WAIT(1);
        } else {
            CP_WAIT(0);
        }
        __syncthreads();

        const float* Qc = Qs + cur * S_TW;
        const float* Kc = Ks + cur * S_TW;
        #pragma unroll
        for (int ks = 0; ks < 4; ks++) {
            int kk = ks * 8;
            uint32_t af[3][4], bf[6][2];
            #pragma unroll
            for (int mt = 0; mt < 3; mt++) {
                int m0 = warpRow + mt * 16;
                af[mt][0] = f2tf32(Qc[(m0 + g)     * SAS + kk + t]);
                af[mt][1] = f2tf32(Qc[(m0 + g + 8) * SAS + kk + t]);
                af[mt][2] = f2tf32(Qc[(m0 + g)     * SAS + kk + t + 4]);
                af[mt][3] = f2tf32(Qc[(m0 + g + 8) * SAS + kk + t + 4]);
            }
            #pragma unroll
            for (int nt = 0; nt < 6; nt++) {
                int n0 = warpCol + nt * 8;
                bf[nt][0] = f2tf32(Kc[(n0 + g) * SAS + kk + t]);
                bf[nt][1] = f2tf32(Kc[(n0 + g) * SAS + kk + t + 4]);
            }
            #pragma unroll
            for (int mt = 0; mt < 3; mt++)
                #pragma unroll
                for (int nt = 0; nt < 6; nt++)
                    mma_tf32(acc[mt][nt], af[mt], bf[nt]);
        }
        __syncthreads();
    }

    // epilogue: scale + bias
    float* ab = attn + (size_t)b * S_ * S_;
    #pragma unroll
    for (int mt = 0; mt < 3; mt++) {
        int m = warpRow + mt * 16 + g;
        #pragma unroll
        for (int nt = 0; nt < 6; nt++) {
            int n = warpCol + nt * 8 + 2 * t;
            float2 bA = *(const float2*)&bias[m * S_ + n];
            float2 bB = *(const float2*)&bias[(m + 8) * S_ + n];
            float2 o0 = { fmaf(acc[mt][nt][0], scale, bA.x),
                          fmaf(acc[mt][nt][1], scale, bA.y) };
            float2 o1 = { fmaf(acc[mt][nt][2], scale, bB.x),
                          fmaf(acc[mt][nt][3], scale, bB.y) };
            *(float2*)&ab[(size_t)m * S_ + n]       = o0;
            *(float2*)&ab[(size_t)(m + 8) * S_ + n] = o1;
        }
    }
}

// ============================================================================
// Kernel 4: softmax over rows of attn
// ============================================================================
__global__ void softmax_kernel(float* __restrict__ attn)
{
    int warp = (blockIdx.x * blockDim.x + threadIdx.x) >> 5;
    int lane = threadIdx.x & 31;
    if (warp >= B_ * S_) return;
    float* row = attn + (size_t)warp * S_;

    float v[5];
    float mx = -INFINITY;
    #pragma unroll
    for (int i = 0; i < 5; i++) {
        int idx = lane + i * 32;
        v[i] = (idx < S_) ? row[idx] : -INFINITY;
        mx = fmaxf(mx, v[i]);
    }
    #pragma unroll
    for (int o = 16; o; o >>= 1) mx = fmaxf(mx, __shfl_xor_sync(0xffffffffu, mx, o));

    float s = 0.f;
    #pragma unroll
    for (int i = 0; i < 5; i++) {
        v[i] = __expf(v[i] - mx);
        s += v[i];
    }
    #pragma unroll
    for (int o = 16; o; o >>= 1) s += __shfl_xor_sync(0xffffffffu, s, o);

    float inv = 1.f / s;
    #pragma unroll
    for (int i = 0; i < 5; i++) {
        int idx = lane + i * 32;
        if (idx < S_) row[idx] = v[i] * inv;
    }
}

// ============================================================================
// Kernel 5: out = attn @ v   -- tf32 MMA
//   grid (8 n-chunks, 128 batches). CTA tile 144x128, K=144 in 3 chunks of 48.
//   12 warps (3x4 @ 48x32). Single-buffered (only 3 k-iterations).
// ============================================================================
#define VAS 52                              // attn smem stride
#define VBS 136                             // v smem stride
#define AV_SMEM ((S_ * VAS + 48 * VBS) * 4) // 56064 B

__global__ __launch_bounds__(384, 1)
void av_tc(const float* __restrict__ attn, const float* __restrict__ v,
           float* __restrict__ out)
{
    extern __shared__ float sm[];
    float* As = sm;                  // [144][52] (tf32 bits)
    float* Vs = sm + S_ * VAS;       // [48][136] (tf32 bits)

    const int b = blockIdx.y;
    const int colBase = blockIdx.x * 128;
    const float* ab = attn + (size_t)b * S_ * S_;
    const float* vb = v + (size_t)b * S_ * D_;

    const int tid  = threadIdx.x;
    const int lane = tid & 31;
    const int warp = tid >> 5;                // 0..11
    const int g = lane >> 2;
    const int t = lane & 3;
    const int warpRow = (warp >> 2) * 48;     // 0,48,96
    const int warpCol = (warp & 3) * 32;      // 0,32,64,96

    float acc[3][4][4];
    #pragma unroll
    for (int i = 0; i < 3; i++)
        #pragma unroll
        for (int j = 0; j < 4; j++)
            #pragma unroll
            for (int r = 0; r < 4; r++) acc[i][j][r] = 0.f;

    for (int k0 = 0; k0 < S_; k0 += 48) {
        // load attn tile (144 x 48): 1728 float4 chunks
        for (int idx = tid; idx < 144 * 12; idx += 384) {
            int r = idx / 12, c = (idx % 12) * 4;
            float4 x = *(const float4*)&ab[(size_t)r * S_ + k0 + c];
            uint4 u = { f2tf32(x.x), f2tf32(x.y), f2tf32(x.z), f2tf32(x.w) };
            *(uint4*)&As[r * VAS + c] = u;
        }
        // load v tile (48 x 128): 1536 float4 chunks -> 4 per thread
        #pragma unroll
        for (int i = 0; i < 4; i++) {
            int idx = tid + i * 384;
            int r = idx >> 5, c = (idx & 31) * 4;
            float4 x = *(const float4*)&vb[(size_t)(k0 + r) * D_ + colBase + c];
            uint4 u = { f2tf32(x.x), f2tf32(x.y), f2tf32(x.z), f2tf32(x.w) };
            *(uint4*)&Vs[r * VBS + c] = u;
        }
        __syncthreads();

        #pragma unroll
        for (int ks = 0; ks < 6; ks++) {
            int kk = ks * 8;
            uint32_t af[3][4], bf[4][2];
            #pragma unroll
            for (int mt = 0; mt < 3; mt++) {
                int m0 = warpRow + mt * 16;
                af[mt][0] = __float_as_uint(As[(m0 + g)     * VAS + kk + t]);
                af[mt][1] = __float_as_uint(As[(m0 + g + 8) * VAS + kk + t]);
                af[mt][2] = __float_as_uint(As[(m0 + g)     * VAS + kk + t + 4]);
                af[mt][3] = __float_as_uint(As[(m0 + g + 8) * VAS + kk + t + 4]);
            }
            #pragma unroll
            for (int nt = 0; nt < 4; nt++) {
                int n0 = warpCol + nt * 8;
                bf[nt][0] = __float_as_uint(Vs[(kk + t)     * VBS + n0 + g]);
                bf[nt][1] = __float_as_uint(Vs[(kk + t + 4) * VBS + n0 + g]);
            }
            #pragma unroll
            for (int mt = 0; mt < 3; mt++)
                #pragma unroll
                for (int nt = 0; nt < 4; nt++)
                    mma_tf32(acc[mt][nt], af[mt], bf[nt]);
        }
        __syncthreads();
    }

    #pragma unroll
    for (int mt = 0; mt < 3; mt++) {
        int m = warpRow + mt * 16 + g;
        #pragma unroll
        for (int nt = 0; nt < 4; nt++) {
            int n = colBase + warpCol + nt * 8 + 2 * t;
            float2 o0 = { acc[mt][nt][0], acc[mt][nt][1] };
            float2 o1 = { acc[mt][nt][2], acc[mt][nt][3] };
            *(float2*)&out[((size_t)b * S_ + m) * D_ + n]       = o0;
            *(float2*)&out[((size_t)b * S_ + m + 8) * D_ + n]   = o1;
        }
    }
}

// ============================================================================
// launch
// ============================================================================
extern "C" void kernel_launch(void* const* d_in, const int* in_sizes, int n_in,
                              void* d_out, int out_size)
{
    const float* query = (const float*)d_in[0];
    const float* key   = (const float*)d_in[1];
    const float* value = (const float*)d_in[2];
    const float* Wq    = (const float*)d_in[3];
    const float* bq    = (const float*)d_in[4];
    const float* Wk    = (const float*)d_in[5];
    const float* bk    = (const float*)d_in[6];
    const float* Wv    = (const float*)d_in[7];
    const float* bv    = (const float*)d_in[8];
    const float* Wl    = (const float*)d_in[9];
    const float* bl    = (const float*)d_in[10];
    const float* wg    = (const float*)d_in[11];
    float* out = (float*)d_out;

    float* q;    cudaGetSymbolAddress((void**)&q,    g_q);
    float* k;    cudaGetSymbolAddress((void**)&k,    g_k);
    float* v;    cudaGetSymbolAddress((void**)&v,    g_v);
    float* attn; cudaGetSymbolAddress((void**)&attn, g_attn);
    float* bias; cudaGetSymbolAddress((void**)&bias, g_bias);

    cudaFuncSetAttribute(proj_gemm_tc,
                         cudaFuncAttributeMaxDynamicSharedMemorySize, PROJ_SMEM);
    cudaFuncSetAttribute(scores_tc,
                         cudaFuncAttributeMaxDynamicSharedMemorySize, SCORES_SMEM);
    cudaFuncSetAttribute(av_tc,
                         cudaFuncAttributeMaxDynamicSharedMemorySize, AV_SMEM);

    // 1. relative-position bias table (batch-independent)
    bias_kernel<<<dim3(S_, S_), 256>>>(Wl, bl, wg, bias);

    // 2. projections (fused into one launch; z selects q/k/v)
    dim3 pg(D_ / PBN, BS_ / PBM, 3);     // (8, 144, 3)
    proj_gemm_tc<<<pg, 256, PROJ_SMEM>>>(query, key, value,
                                         Wq, Wk, Wv, bq, bk, bv,
                                         q, k, v);

    // 3. scores (+ scale + bias): one CTA per batch
    float scale = 1.0f / sqrtf((float)D_);
    scores_tc<<<B_, 288, SCORES_SMEM>>>(q, k, bias, attn, scale);

    // 4. softmax
    int rows = B_ * S_;
    softmax_kernel<<<(rows * 32 + 255) / 256, 256>>>(attn);

    // 5. out = attn @ v
    av_tc<<<dim3(D_ / 128, B_), 384, AV_SMEM>>>(attn, v, out);
}

// round 5
// speedup vs baseline: 4.7941x; 1.2969x over previous
#include <cuda_runtime.h>
#include <cuda_fp16.h>
#include <math.h>
#include <stdint.h>

// ============================================================================
// RegionAugmentedSelfAttention  (B=128, S=144, D=1024, GRID=12)
//   R5: fp16 mma.sync.m16n8k16 everywhere (same 11-bit significand as tf32,
//       2x HMMA throughput, no in-loop cvt). q/k/v stored fp16.
//       Bias restructured: 144-combo rel table + tiny GEMM + scatter.
//   (tcgen05 unavailable: harness PTX target is compute_103, ptxas rejects it)
// ============================================================================

#define B_  128
#define S_  144
#define D_  1024
#define BS_ (B_ * S_)          // 18432

// -------- scratch (static device globals: no runtime allocation) -----------
__device__ __align__(16) unsigned short g_q[BS_ * D_];     // half
__device__ __align__(16) unsigned short g_k[BS_ * D_];     // half
__device__ __align__(16) unsigned short g_v[BS_ * D_];     // half
__device__ __align__(16) unsigned short g_wt[3 * D_ * D_]; // half W^T (n,k)
__device__ float g_attn[B_ * S_ * S_];
__device__ float g_bias[S_ * S_];
__device__ float g_R[144 * D_];     // rel table per (|dr|,|dc|) combo
__device__ float g_T[S_ * S_];      // T[i][combo]

// ---------------------------------------------------------------------------
// helpers
// ---------------------------------------------------------------------------
__device__ __forceinline__ uint32_t pack_h2(float lo, float hi) {
    uint32_t r;
    asm("cvt.rn.f16x2.f32 %0, %1, %2;" : "=r"(r) : "f"(hi), "f"(lo));
    return r;
}

__device__ __forceinline__ void mma_h(float (&d)[4],
                                      const uint32_t (&a)[4],
                                      const uint32_t (&b)[2]) {
    asm volatile(
        "mma.sync.aligned.m16n8k16.row.col.f32.f16.f16.f32 "
        "{%0,%1,%2,%3}, {%4,%5,%6,%7}, {%8,%9}, {%0,%1,%2,%3};\n"
        : "+f"(d[0]), "+f"(d[1]), "+f"(d[2]), "+f"(d[3])
        : "r"(a[0]), "r"(a[1]), "r"(a[2]), "r"(a[3]),
          "r"(b[0]), "r"(b[1]));
}

__device__ __forceinline__ void cp_async16(uint32_t smem_addr, const void* gptr) {
    asm volatile("cp.async.cg.shared.global [%0], [%1], 16;\n"
                 :: "r"(smem_addr), "l"(gptr));
}
#define CP_COMMIT()  asm volatile("cp.async.commit_group;\n")
#define CP_WAIT(N)   asm volatile("cp.async.wait_group %0;\n" :: "n"(N))

__device__ __forceinline__ uint32_t smem_u32p(const void* p) {
    return (uint32_t)__cvta_generic_to_shared(p);
}

// ============================================================================
// Bias pipeline (batch-independent, 3 tiny kernels)
// ============================================================================
// 1) rel table: R[c][d] = relu(dx_a*Wl0[d] + dy_b*Wl1[d] + bl[d]),
//    c = a*12+b over (|dr|,|dc|) combos (dw=dh=0 since w=h=2 everywhere)
__global__ void rel_kernel(const float* __restrict__ Wl,
                           const float* __restrict__ bl,
                           float* __restrict__ R)
{
    int c = blockIdx.x;
    int a = c / 12, b = c % 12;
    float dx = logf(fmaxf((float)a * 0.5f, 1e-10f));
    float dy = logf(fmaxf((float)b * 0.5f, 1e-10f));
    for (int d = threadIdx.x; d < D_; d += blockDim.x)
        R[c * D_ + d] = fmaxf(fmaf(dx, Wl[d], fmaf(dy, Wl[D_ + d], bl[d])), 0.f);
}

// 2) T[i][c] = sum_d wg[i][d] * R[c][d]   (144x144x1024 fp32 GEMM, tiny)
__global__ __launch_bounds__(256)
void tgemm(const float* __restrict__ wg, const float* __restrict__ R,
           float* __restrict__ T)
{
    __shared__ float As[16][48];
    __shared__ float Bs[16][48];
    int tid = threadIdx.x;
    int tx = tid & 15, ty = tid >> 4;
    int rowBase = blockIdx.y * 48;
    int colBase = blockIdx.x * 48;

    float acc[3][3] = {};
    for (int k0 = 0; k0 < D_; k0 += 16) {
        for (int idx = tid; idx < 48 * 16; idx += 256) {
            int r = idx >> 4, kk = idx & 15;
            As[kk][r] = wg[(size_t)(rowBase + r) * D_ + k0 + kk];
            Bs[kk][r] = R[(size_t)(colBase + r) * D_ + k0 + kk];
        }
        __syncthreads();
        #pragma unroll
        for (int kk = 0; kk < 16; kk++) {
            float ra[3], rb[3];
            #pragma unroll
            for (int i = 0; i < 3; i++) ra[i] = As[kk][ty * 3 + i];
            #pragma unroll
            for (int j = 0; j < 3; j++) rb[j] = Bs[kk][tx * 3 + j];
            #pragma unroll
            for (int i = 0; i < 3; i++)
                #pragma unroll
                for (int j = 0; j < 3; j++)
                    acc[i][j] = fmaf(ra[i], rb[j], acc[i][j]);
        }
        __syncthreads();
    }
    #pragma unroll
    for (int i = 0; i < 3; i++)
        #pragma unroll
        for (int j = 0; j < 3; j++)
            T[(size_t)(rowBase + ty * 3 + i) * S_ + colBase + tx * 3 + j] = acc[i][j];
}

// 3) scatter: bias[i][j] = relu(T[i][combo(i,j)])
__global__ void scatter_bias(const float* __restrict__ T, float* __restrict__ bias)
{
    int idx = blockIdx.x * 256 + threadIdx.x;
    if (idx >= S_ * S_) return;
    int i = idx / S_, j = idx % S_;
    int dr = abs(i / 12 - j / 12);
    int dc = abs(i % 12 - j % 12);
    bias[idx] = fmaxf(T[i * S_ + dr * 12 + dc], 0.f);
}

// ============================================================================
// transpose + convert weights:  Wt[z][n][k] = half(W_z[k][n])
// ============================================================================
__global__ void transpose_w(const float* __restrict__ Wq,
                            const float* __restrict__ Wk,
                            const float* __restrict__ Wv,
                            __half* __restrict__ Wt)
{
    __shared__ float t[32][33];
    const float* W = (blockIdx.z == 0) ? Wq : (blockIdx.z == 1) ? Wk : Wv;
    __half* O = Wt + (size_t)blockIdx.z * D_ * D_;
    int x0 = blockIdx.x * 32, y0 = blockIdx.y * 32;
    #pragma unroll
    for (int r = threadIdx.y; r < 32; r += 8)
        t[r][threadIdx.x] = W[(size_t)(y0 + r) * D_ + x0 + threadIdx.x];
    __syncthreads();
    #pragma unroll
    for (int r = threadIdx.y; r < 32; r += 8)
        O[(size_t)(x0 + r) * D_ + y0 + threadIdx.x] = __float2half(t[threadIdx.x][r]);
}

// ============================================================================
// Projection GEMM  C = relu(A @ W + b)  -- fp16 mma.sync.m16n8k16
//   A (M,K) fp32 global -> LDG+cvt+STS;  W^T (N,K) half global -> cp.async.
//   CTA tile 128x128, BK=32, double-buffered, 8 warps @ 64x32.
//   smem (half2 words, stride 20): A [128][20], B [128][20] per stage.
// ============================================================================
#define P_STAGE_W 5120                      // u32 words per stage (A 2560 + B 2560)
#define PROJ_SMEM (2 * P_STAGE_W * 4)       // 40960 B

__global__ __launch_bounds__(256, 2)
void proj_h(const float* __restrict__ Aq, const float* __restrict__ Ak,
            const float* __restrict__ Av,
            const __half* __restrict__ Wt,
            const float* __restrict__ bq, const float* __restrict__ bk,
            const float* __restrict__ bv,
            __half* __restrict__ Cq, __half* __restrict__ Ck,
            __half* __restrict__ Cv)
{
    extern __shared__ uint32_t smu[];
    const uint32_t sb = smem_u32p(smu);

    const float *A, *bvec;
    __half* C;
    if (blockIdx.z == 0)      { A = Aq; bvec = bq; C = Cq; }
    else if (blockIdx.z == 1) { A = Ak; bvec = bk; C = Ck; }
    else                      { A = Av; bvec = bv; C = Cv; }
    const __half* Bt = Wt + (size_t)blockIdx.z * D_ * D_;

    const int tid  = threadIdx.x;
    const int lane = tid & 31;
    const int warp = tid >> 5;
    const int g = lane >> 2;
    const int t = lane & 3;
    const int rowBase = blockIdx.y * 128;
    const int colBase = blockIdx.x * 128;
    const int warpRow = (warp >> 2) * 64;
    const int warpCol = (warp & 3) * 32;

    // A loader: thread covers rows r0+32j (j<4), float4 chunk ca
    const int r0 = tid >> 3;            // 0..31
    const int ca = tid & 7;             // 0..7
    const float* Ag = A + (size_t)(rowBase + r0) * D_ + ca * 4;
    const int aWordBase = r0 * 20 + ca * 2;   // half2-word index within A block

    // B loader: thread covers rows rb+64j (j<2), 16B chunk cb  (cp.async)
    const int rb = tid >> 2;            // 0..63
    const int cb = tid & 3;             // 0..3
    const __half* Bg = Bt + (size_t)(colBase + rb) * D_ + cb * 8;
    const uint32_t bSb = sb + 10240 + rb * 80 + cb * 16;  // byte addr, B at +2560 words

    float acc[4][4][4];
    #pragma unroll
    for (int i = 0; i < 4; i++)
        #pragma unroll
        for (int j = 0; j < 4; j++)
            #pragma unroll
            for (int r = 0; r < 4; r++) acc[i][j][r] = 0.f;

    float4 ra[4];

    // ---- prologue: tile 0 -> stage 0 ----
    #pragma unroll
    for (int j = 0; j < 4; j++)
        ra[j] = *(const float4*)(Ag + (size_t)(j * 32) * D_);
    #pragma unroll
    for (int j = 0; j < 2; j++)
        cp_async16(bSb + j * 5120, Bg + (size_t)(j * 64) * D_);
    CP_COMMIT();
    #pragma unroll
    for (int j = 0; j < 4; j++) {
        uint2 pp = { pack_h2(ra[j].x, ra[j].y), pack_h2(ra[j].z, ra[j].w) };
        *(uint2*)&smu[aWordBase + j * 640] = pp;
    }
    CP_WAIT(0);
    __syncthreads();

    const int NKT = D_ / 32;   // 32
    for (int kt = 0; kt < NKT; kt++) {
        const int cur = kt & 1;
        const int nxt = cur ^ 1;
        if (kt + 1 < NKT) {
            #pragma unroll
            for (int j = 0; j < 4; j++)
                ra[j] = *(const float4*)(Ag + (size_t)(j * 32) * D_ + (kt + 1) * 32);
            #pragma unroll
            for (int j = 0; j < 2; j++)
                cp_async16(bSb + nxt * 20480 + j * 5120,
                           Bg + (size_t)(j * 64) * D_ + (kt + 1) * 32);
            CP_COMMIT();
        }

        // compute current stage
        const uint32_t* Ac = smu + cur * P_STAGE_W;
        const uint32_t* Bc = smu + cur * P_STAGE_W + 2560;
        #pragma unroll
        for (int ks = 0; ks < 2; ks++) {
            const int kd = ks * 8;
            uint32_t af[4][4], bf[4][2];
            #pragma unroll
            for (int mt = 0; mt < 4; mt++) {
                int m0 = warpRow + mt * 16;
                af[mt][0] = Ac[(m0 + g)     * 20 + kd + t];
                af[mt][1] = Ac[(m0 + g + 8) * 20 + kd + t];
                af[mt][2] = Ac[(m0 + g)     * 20 + kd + t + 4];
                af[mt][3] = Ac[(m0 + g + 8) * 20 + kd + t + 4];
            }
            #pragma unroll
            for (int nt = 0; nt < 4; nt++) {
                int n0 = warpCol + nt * 8;
                bf[nt][0] = Bc[(n0 + g) * 20 + kd + t];
                bf[nt][1] = Bc[(n0 + g) * 20 + kd + t + 4];
            }
            #pragma unroll
            for (int mt = 0; mt < 4; mt++)
                #pragma unroll
                for (int nt = 0; nt < 4; nt++)
                    mma_h(acc[mt][nt], af[mt], bf[nt]);
        }

        if (kt + 1 < NKT) {
            #pragma unroll
            for (int j = 0; j < 4; j++) {
                uint2 pp = { pack_h2(ra[j].x, ra[j].y), pack_h2(ra[j].z, ra[j].w) };
                *(uint2*)&smu[nxt * P_STAGE_W + aWordBase + j * 640] = pp;
            }
            CP_WAIT(0);
        }
        __syncthreads();
    }

    // ---- epilogue: bias + relu -> half2 stores ----
    #pragma unroll
    for (int mt = 0; mt < 4; mt++) {
        int r = rowBase + warpRow + mt * 16 + g;
        #pragma unroll
        for (int nt = 0; nt < 4; nt++) {
            int c = colBase + warpCol + nt * 8 + 2 * t;
            float b0 = bvec[c], b1 = bvec[c + 1];
            uint32_t h0 = pack_h2(fmaxf(acc[mt][nt][0] + b0, 0.f),
                                  fmaxf(acc[mt][nt][1] + b1, 0.f));
            uint32_t h1 = pack_h2(fmaxf(acc[mt][nt][2] + b0, 0.f),
                                  fmaxf(acc[mt][nt][3] + b1, 0.f));
            *(uint32_t*)&C[(size_t)r * D_ + c]       = h0;
            *(uint32_t*)&C[(size_t)(r + 8) * D_ + c] = h1;
        }
    }
}

// ============================================================================
// scores: attn[b] = q_b @ k_b^T * scale + bias   -- fp16 mma
//   One CTA per batch, 9 warps (3x3 @ 48x48), BK=32 halves, cp.async 2-stage.
//   smem stride 20 half2-words per row (conflict-free).
// ============================================================================
#define S_STAGE_W 5760                       // Q 2880 + K 2880 per stage
#define SCORES_SMEM (2 * S_STAGE_W * 4)      // 46080 B

__global__ __launch_bounds__(288, 1)
void scores_h(const __half* __restrict__ q, const __half* __restrict__ k,
              const float* __restrict__ bias, float* __restrict__ attn,
              float scale)
{
    extern __shared__ uint32_t smu[];
    const uint32_t sb = smem_u32p(smu);

    const int b = blockIdx.x;
    const __half* qb = q + (size_t)b * S_ * D_;
    const __half* kb = k + (size_t)b * S_ * D_;

    const int tid  = threadIdx.x;
    const int lane = tid & 31;
    const int warp = tid >> 5;
    const int g = lane >> 2;
    const int t = lane & 3;
    const int warpRow = (warp / 3) * 48;
    const int warpCol = (warp % 3) * 48;

    // loaders: row r, two 16B chunks {c, c+2} of the 64B row slice
    const int r = tid >> 1;              // 0..143
    const int c0 = tid & 1;
    const __half* qg = qb + (size_t)r * D_;
    const __half* kg = kb + (size_t)r * D_;
    const uint32_t qSb = sb + r * 80;
    const uint32_t kSb = sb + 11520 + r * 80;

    float acc[3][6][4];
    #pragma unroll
    for (int i = 0; i < 3; i++)
        #pragma unroll
        for (int j = 0; j < 6; j++)
            #pragma unroll
            for (int rr = 0; rr < 4; rr++) acc[i][j][rr] = 0.f;

    const int NKT = D_ / 32;   // 32

    // prologue
    #pragma unroll
    for (int j = 0; j < 2; j++) {
        int ch = c0 + j * 2;
        cp_async16(qSb + ch * 16, qg + ch * 8);
        cp_async16(kSb + ch * 16, kg + ch * 8);
    }
    CP_COMMIT();

    for (int kt = 0; kt < NKT; kt++) {
        const int cur = kt & 1;
        if (kt + 1 < NKT) {
            const int nxt = cur ^ 1;
            #pragma unroll
            for (int j = 0; j < 2; j++) {
                int ch = c0 + j * 2;
                cp_async16(qSb + nxt * 23040 + ch * 16, qg + (kt + 1) * 32 + ch * 8);
                cp_async16(kSb + nxt * 23040 + ch * 16, kg + (kt + 1) * 32 + ch * 8);
            }
            CP_COMMIT();
            CP_WAIT(1);
        } else {
            CP_WAIT(0);
        }
        __syncthreads();

        const uint32_t* Qc = smu + cur * S_STAGE_W;
        const uint32_t* Kc = smu + cur * S_STAGE_W + 2880;
        #pragma unroll
        for (int ks = 0; ks < 2; ks++) {
            const int kd = ks * 8;
            uint32_t af[3][4], bf[6][2];
            #pragma unroll
            for (int mt = 0; mt < 3; mt++) {
                int m0 = warpRow + mt * 16;
                af[mt][0] = Qc[(m0 + g)     * 20 + kd + t];
                af[mt][1] = Qc[(m0 + g + 8) * 20 + kd + t];
                af[mt][2] = Qc[(m0 + g)     * 20 + kd + t + 4];
                af[mt][3] = Qc[(m0 + g + 8) * 20 + kd + t + 4];
            }
            #pragma unroll
            for (int nt = 0; nt < 6; nt++) {
                int n0 = warpCol + nt * 8;
                bf[nt][0] = Kc[(n0 + g) * 20 + kd + t];
                bf[nt][1] = Kc[(n0 + g) * 20 + kd + t + 4];
            }
            #pragma unroll
            for (int mt = 0; mt < 3; mt++)
                #pragma unroll
                for (int nt = 0; nt < 6; nt++)
                    mma_h(acc[mt][nt], af[mt], bf[nt]);
        }
        __syncthreads();
    }

    float* ab = attn + (size_t)b * S_ * S_;
    #pragma unroll
    for (int mt = 0; mt < 3; mt++) {
        int m = warpRow + mt * 16 + g;
        #pragma unroll
        for (int nt = 0; nt < 6; nt++) {
            int n = warpCol + nt * 8 + 2 * t;
            float2 bA = *(const float2*)&bias[m * S_ + n];
            float2 bB = *(const float2*)&bias[(m + 8) * S_ + n];
            float2 o0 = { fmaf(acc[mt][nt][0], scale, bA.x),
                          fmaf(acc[mt][nt][1], scale, bA.y) };
            float2 o1 = { fmaf(acc[mt][nt][2], scale, bB.x),
                          fmaf(acc[mt][nt][3], scale, bB.y) };
            *(float2*)&ab[(size_t)m * S_ + n]       = o0;
            *(float2*)&ab[(size_t)(m + 8) * S_ + n] = o1;
        }
    }
}

// ============================================================================
// softmax over rows of attn (fp32)
// ============================================================================
__global__ void softmax_kernel(float* __restrict__ attn)
{
    int warp = (blockIdx.x * blockDim.x + threadIdx.x) >> 5;
    int lane = threadIdx.x & 31;
    if (warp >= B_ * S_) return;
    float* row = attn + (size_t)warp * S_;

    float v[5];
    float mx = -INFINITY;
    #pragma unroll
    for (int i = 0; i < 5; i++) {
        int idx = lane + i * 32;
        v[i] = (idx < S_) ? row[idx] : -INFINITY;
        mx = fmaxf(mx, v[i]);
    }
    #pragma unroll
    for (int o = 16; o; o >>= 1) mx = fmaxf(mx, __shfl_xor_sync(0xffffffffu, mx, o));

    float s = 0.f;
    #pragma unroll
    for (int i = 0; i < 5; i++) {
        v[i] = __expf(v[i] - mx);
        s += v[i];
    }
    #pragma unroll
    for (int o = 16; o; o >>= 1) s += __shfl_xor_sync(0xffffffffu, s, o);

    float inv = 1.f / s;
    #pragma unroll
    for (int i = 0; i < 5; i++) {
        int idx = lane + i * 32;
        if (idx < S_) row[idx] = v[i] * inv;
    }
}

// ============================================================================
// out = attn @ v  -- fp16 mma.  attn fp32 -> half on smem store; v tile
// transposed into smem [d][token].  grid (8 n-chunks, 128 batches), 12 warps.
//   smem: attnH [144][28] u32 (4032) + Vs [128][28] u32 (3584) = 30464 B
// ============================================================================
#define AV_SMEM ((144 * 28 + 128 * 28) * 4)

__global__ __launch_bounds__(384, 1)
void av_h(const float* __restrict__ attn, const __half* __restrict__ v,
          float* __restrict__ out)
{
    extern __shared__ uint32_t smu[];
    uint32_t* An = smu;               // [144][28] half2 words
    uint32_t* Vs = smu + 144 * 28;    // [128][28] half2 words

    const int b = blockIdx.y;
    const int colBase = blockIdx.x * 128;
    const float*  ab = attn + (size_t)b * S_ * S_;
    const __half* vb = v + (size_t)b * S_ * D_;

    const int tid  = threadIdx.x;
    const int lane = tid & 31;
    const int warp = tid >> 5;
    const int g = lane >> 2;
    const int t = lane & 3;
    const int warpRow = (warp >> 2) * 48;     // 0,48,96
    const int warpCol = (warp & 3) * 32;      // 0,32,64,96

    float acc[3][4][4];
    #pragma unroll
    for (int i = 0; i < 3; i++)
        #pragma unroll
        for (int j = 0; j < 4; j++)
            #pragma unroll
            for (int r = 0; r < 4; r++) acc[i][j][r] = 0.f;

    for (int k0 = 0; k0 < S_; k0 += 48) {
        // attn tile (144 x 48 fp32) -> half, [row][k half2]
        for (int idx = tid; idx < 144 * 12; idx += 384) {
            int rr = idx / 12, cc = idx % 12;
            float4 x = *(const float4*)&ab[(size_t)rr * S_ + k0 + cc * 4];
            uint2 pp = { pack_h2(x.x, x.y), pack_h2(x.z, x.w) };
            *(uint2*)&An[rr * 28 + cc * 2] = pp;
        }
        // v tile (48 tokens x 128 d, half) -> transposed smem [d][token]
        unsigned short* vs16 = (unsigned short*)Vs;
        #pragma unroll
        for (int j = 0; j < 2; j++) {
            int idx = tid + j * 384;          // 0..767
            int tk = idx >> 4;                // token 0..47
            int dch = idx & 15;               // d-chunk of 8
            uint4 u = *(const uint4*)&vb[(size_t)(k0 + tk) * D_ + colBase + dch * 8];
            const unsigned short* hs = (const unsigned short*)&u;
            #pragma unroll
            for (int e = 0; e < 8; e++)
                vs16[(dch * 8 + e) * 56 + tk] = hs[e];
        }
        __syncthreads();

        #pragma unroll
        for (int ks = 0; ks < 3; ks++) {
            const int kd = ks * 8;
            uint32_t af[3][4], bf[4][2];
            #pragma unroll
            for (int mt = 0; mt < 3; mt++) {
                int m0 = warpRow + mt * 16;
                af[mt][0] = An[(m0 + g)     * 28 + kd + t];
                af[mt][1] = An[(m0 + g + 8) * 28 + kd + t];
                af[mt][2] = An[(m0 + g)     * 28 + kd + t + 4];
                af[mt][3] = An[(m0 + g + 8) * 28 + kd + t + 4];
            }
            #pragma unroll
            for (int nt = 0; nt < 4; nt++) {
                int n0 = warpCol + nt * 8;
                bf[nt][0] = Vs[(n0 + g) * 28 + kd + t];
                bf[nt][1] = Vs[(n0 + g) * 28 + kd + t + 4];
            }
            #pragma unroll
            for (int mt = 0; mt < 3; mt++)
                #pragma unroll
                for (int nt = 0; nt < 4; nt++)
                    mma_h(acc[mt][nt], af[mt], bf[nt]);
        }
        __syncthreads();
    }

    #pragma unroll
    for (int mt = 0; mt < 3; mt++) {
        int m = warpRow + mt * 16 + g;
        #pragma unroll
        for (int nt = 0; nt < 4; nt++) {
            int n = colBase + warpCol + nt * 8 + 2 * t;
            float2 o0 = { acc[mt][nt][0], acc[mt][nt][1] };
            float2 o1 = { acc[mt][nt][2], acc[mt][nt][3] };
            *(float2*)&out[((size_t)b * S_ + m) * D_ + n]     = o0;
            *(float2*)&out[((size_t)b * S_ + m + 8) * D_ + n] = o1;
        }
    }
}

// ============================================================================
// launch
// ============================================================================
extern "C" void kernel_launch(void* const* d_in, const int* in_sizes, int n_in,
                              void* d_out, int out_size)
{
    const float* query = (const float*)d_in[0];
    const float* key   = (const float*)d_in[1];
    const float* value = (const float*)d_in[2];
    const float* Wq    = (const float*)d_in[3];
    const float* bq    = (const float*)d_in[4];
    const float* Wk    = (const float*)d_in[5];
    const float* bk    = (const float*)d_in[6];
    const float* Wv    = (const float*)d_in[7];
    const float* bv    = (const float*)d_in[8];
    const float* Wl    = (const float*)d_in[9];
    const float* bl    = (const float*)d_in[10];
    const float* wg    = (const float*)d_in[11];
    float* out = (float*)d_out;

    __half* qh;  cudaGetSymbolAddress((void**)&qh,  g_q);
    __half* kh;  cudaGetSymbolAddress((void**)&kh,  g_k);
    __half* vh;  cudaGetSymbolAddress((void**)&vh,  g_v);
    __half* wt;  cudaGetSymbolAddress((void**)&wt,  g_wt);
    float* attn; cudaGetSymbolAddress((void**)&attn, g_attn);
    float* bias; cudaGetSymbolAddress((void**)&bias, g_bias);
    float* R;    cudaGetSymbolAddress((void**)&R,    g_R);
    float* T;    cudaGetSymbolAddress((void**)&T,    g_T);

    cudaFuncSetAttribute(proj_h,
                         cudaFuncAttributeMaxDynamicSharedMemorySize, PROJ_SMEM);
    cudaFuncSetAttribute(scores_h,
                         cudaFuncAttributeMaxDynamicSharedMemorySize, SCORES_SMEM);
    cudaFuncSetAttribute(av_h,
                         cudaFuncAttributeMaxDynamicSharedMemorySize, AV_SMEM);

    // bias pipeline (cheap) + weight transpose
    rel_kernel<<<144, 256>>>(Wl, bl, R);
    tgemm<<<dim3(3, 3), 256>>>(wg, R, T);
    scatter_bias<<<81, 256>>>(T, bias);
    transpose_w<<<dim3(32, 32, 3), dim3(32, 8)>>>(Wq, Wk, Wv, wt);

    // projections (fp16 HMMA)
    proj_h<<<dim3(8, 144, 3), 256, PROJ_SMEM>>>(query, key, value, wt,
                                                bq, bk, bv, qh, kh, vh);

    // scores (+ scale + bias): one CTA per batch
    float scale = 1.0f / sqrtf((float)D_);
    scores_h<<<B_, 288, SCORES_SMEM>>>(qh, kh, bias, attn, scale);

    // softmax
    int rows = B_ * S_;
    softmax_kernel<<<(rows * 32 + 255) / 256, 256>>>(attn);

    // out = attn @ v
    av_h<<<dim3(D_ / 128, B_), 384, AV_SMEM>>>(attn, vh, out);
}

// round 6
// speedup vs baseline: 4.8631x; 1.0144x over previous
#include <cuda_runtime.h>
#include <cuda_fp16.h>
#include <math.h>
#include <stdint.h>

// ============================================================================
// RegionAugmentedSelfAttention  (B=128, S=144, D=1024, GRID=12)
//   R6: proj main loop = cp.async (both operands, fp16 preconverted) +
//       ldmatrix.x4 fragment loads + 3-stage pipeline.
// ============================================================================

#define B_  128
#define S_  144
#define D_  1024
#define BS_ (B_ * S_)          // 18432

// -------- scratch (static device globals) -----------------------------------
__device__ __align__(16) unsigned short g_ah[3 * BS_ * D_];  // half q/k/v inputs
__device__ __align__(16) unsigned short g_q[BS_ * D_];
__device__ __align__(16) unsigned short g_k[BS_ * D_];
__device__ __align__(16) unsigned short g_v[BS_ * D_];
__device__ __align__(16) unsigned short g_wt[3 * D_ * D_];   // half W^T (n,k)
__device__ float g_attn[B_ * S_ * S_];
__device__ float g_bias[S_ * S_];
__device__ float g_R[144 * D_];
__device__ float g_T[S_ * S_];

// ---------------------------------------------------------------------------
// helpers
// ---------------------------------------------------------------------------
__device__ __forceinline__ uint32_t pack_h2(float lo, float hi) {
    uint32_t r;
    asm("cvt.rn.f16x2.f32 %0, %1, %2;" : "=r"(r) : "f"(hi), "f"(lo));
    return r;
}

__device__ __forceinline__ void mma_h(float (&d)[4],
                                      const uint32_t (&a)[4],
                                      const uint32_t (&b)[2]) {
    asm volatile(
        "mma.sync.aligned.m16n8k16.row.col.f32.f16.f16.f32 "
        "{%0,%1,%2,%3}, {%4,%5,%6,%7}, {%8,%9}, {%0,%1,%2,%3};\n"
        : "+f"(d[0]), "+f"(d[1]), "+f"(d[2]), "+f"(d[3])
        : "r"(a[0]), "r"(a[1]), "r"(a[2]), "r"(a[3]),
          "r"(b[0]), "r"(b[1]));
}

__device__ __forceinline__ void ldsm_x4(uint32_t (&r)[4], uint32_t addr) {
    asm volatile("ldmatrix.sync.aligned.m8n8.x4.shared.b16 {%0,%1,%2,%3}, [%4];"
                 : "=r"(r[0]), "=r"(r[1]), "=r"(r[2]), "=r"(r[3]) : "r"(addr));
}

__device__ __forceinline__ void cp_async16(uint32_t smem_addr, const void* gptr) {
    asm volatile("cp.async.cg.shared.global [%0], [%1], 16;\n"
                 :: "r"(smem_addr), "l"(gptr));
}
#define CP_COMMIT()  asm volatile("cp.async.commit_group;\n")
#define CP_WAIT(N)   asm volatile("cp.async.wait_group %0;\n" :: "n"(N))

__device__ __forceinline__ uint32_t smem_u32p(const void* p) {
    return (uint32_t)__cvta_generic_to_shared(p);
}

// ============================================================================
// input fp32 -> fp16 (8 elems / thread)
// ============================================================================
__global__ void a2h(const float* __restrict__ q, const float* __restrict__ k,
                    const float* __restrict__ v, __half* __restrict__ out)
{
    const size_t per = (size_t)BS_ * D_ / 8;     // 2359296
    size_t i = (size_t)blockIdx.x * 256 + threadIdx.x;
    const float* src;
    size_t off;
    if (i < per)           { src = q; off = i; }
    else if (i < 2 * per)  { src = k; off = i - per; }
    else                   { src = v; off = i - 2 * per; }
    float4 x0 = ((const float4*)src)[off * 2];
    float4 x1 = ((const float4*)src)[off * 2 + 1];
    uint4 u = { pack_h2(x0.x, x0.y), pack_h2(x0.z, x0.w),
                pack_h2(x1.x, x1.y), pack_h2(x1.z, x1.w) };
    ((uint4*)out)[i] = u;
}

// ============================================================================
// Bias pipeline (batch-independent)
// ============================================================================
__global__ void rel_kernel(const float* __restrict__ Wl,
                           const float* __restrict__ bl,
                           float* __restrict__ R)
{
    int c = blockIdx.x;
    int a = c / 12, b = c % 12;
    float dx = logf(fmaxf((float)a * 0.5f, 1e-10f));
    float dy = logf(fmaxf((float)b * 0.5f, 1e-10f));
    for (int d = threadIdx.x; d < D_; d += blockDim.x)
        R[c * D_ + d] = fmaxf(fmaf(dx, Wl[d], fmaf(dy, Wl[D_ + d], bl[d])), 0.f);
}

__global__ __launch_bounds__(256)
void tgemm(const float* __restrict__ wg, const float* __restrict__ R,
           float* __restrict__ T)
{
    __shared__ float As[16][48];
    __shared__ float Bs[16][48];
    int tid = threadIdx.x;
    int tx = tid & 15, ty = tid >> 4;
    int rowBase = blockIdx.y * 48;
    int colBase = blockIdx.x * 48;

    float acc[3][3] = {};
    for (int k0 = 0; k0 < D_; k0 += 16) {
        for (int idx = tid; idx < 48 * 16; idx += 256) {
            int r = idx >> 4, kk = idx & 15;
            As[kk][r] = wg[(size_t)(rowBase + r) * D_ + k0 + kk];
            Bs[kk][r] = R[(size_t)(colBase + r) * D_ + k0 + kk];
        }
        __syncthreads();
        #pragma unroll
        for (int kk = 0; kk < 16; kk++) {
            float ra[3], rb[3];
            #pragma unroll
            for (int i = 0; i < 3; i++) ra[i] = As[kk][ty * 3 + i];
            #pragma unroll
            for (int j = 0; j < 3; j++) rb[j] = Bs[kk][tx * 3 + j];
            #pragma unroll
            for (int i = 0; i < 3; i++)
                #pragma unroll
                for (int j = 0; j < 3; j++)
                    acc[i][j] = fmaf(ra[i], rb[j], acc[i][j]);
        }
        __syncthreads();
    }
    #pragma unroll
    for (int i = 0; i < 3; i++)
        #pragma unroll
        for (int j = 0; j < 3; j++)
            T[(size_t)(rowBase + ty * 3 + i) * S_ + colBase + tx * 3 + j] = acc[i][j];
}

__global__ void scatter_bias(const float* __restrict__ T, float* __restrict__ bias)
{
    int idx = blockIdx.x * 256 + threadIdx.x;
    if (idx >= S_ * S_) return;
    int i = idx / S_, j = idx % S_;
    int dr = abs(i / 12 - j / 12);
    int dc = abs(i % 12 - j % 12);
    bias[idx] = fmaxf(T[i * S_ + dr * 12 + dc], 0.f);
}

// ============================================================================
// transpose + convert weights:  Wt[z][n][k] = half(W_z[k][n])
// ============================================================================
__global__ void transpose_w(const float* __restrict__ Wq,
                            const float* __restrict__ Wk,
                            const float* __restrict__ Wv,
                            __half* __restrict__ Wt)
{
    __shared__ float t[32][33];
    const float* W = (blockIdx.z == 0) ? Wq : (blockIdx.z == 1) ? Wk : Wv;
    __half* O = Wt + (size_t)blockIdx.z * D_ * D_;
    int x0 = blockIdx.x * 32, y0 = blockIdx.y * 32;
    #pragma unroll
    for (int r = threadIdx.y; r < 32; r += 8)
        t[r][threadIdx.x] = W[(size_t)(y0 + r) * D_ + x0 + threadIdx.x];
    __syncthreads();
    #pragma unroll
    for (int r = threadIdx.y; r < 32; r += 8)
        O[(size_t)(x0 + r) * D_ + y0 + threadIdx.x] = __float2half(t[threadIdx.x][r]);
}

// ============================================================================
// Projection GEMM  C = relu(A @ W + b)  -- fp16 HMMA, lean inner loop
//   A (M,K) half, W^T (N,K) half: both via cp.async, 3-stage pipeline.
//   CTA 128x128, BK=32, 8 warps @ 64x32. Fragments via ldmatrix.x4.
//   smem rows: 32 halves (64B data) + 16B pad = 80B stride. Stage = 20480B.
// ============================================================================
#define P3_STAGE 20480
#define PROJ_SMEM (3 * P3_STAGE)        // 61440 B

__global__ __launch_bounds__(256, 2)
void proj_h2(const __half* __restrict__ Ah, const __half* __restrict__ Wt,
             const float* __restrict__ bq, const float* __restrict__ bk,
             const float* __restrict__ bv,
             __half* __restrict__ Cq, __half* __restrict__ Ck,
             __half* __restrict__ Cv)
{
    extern __shared__ char smc[];
    const uint32_t sb = smem_u32p(smc);

    const int z = blockIdx.z;
    const __half* A  = Ah + (size_t)z * BS_ * D_;
    const __half* Bt = Wt + (size_t)z * D_ * D_;
    const float* bvec = (z == 0) ? bq : (z == 1) ? bk : bv;
    __half* C = (z == 0) ? Cq : (z == 1) ? Ck : Cv;

    const int tid  = threadIdx.x;
    const int lane = tid & 31;
    const int warp = tid >> 5;
    const int rowBase = blockIdx.y * 128;
    const int colBase = blockIdx.x * 128;
    const int warpRow = (warp >> 2) * 64;
    const int warpCol = (warp & 3) * 32;

    // ---- loader mapping: j=0,1 -> rows (tid>>2)+64j, 16B chunk tid&3 ----
    const int lr = tid >> 2;            // 0..63
    const int lc = tid & 3;             // 0..3
    const __half* Aga = A  + (size_t)(rowBase + lr) * D_ + lc * 8;
    const __half* Agb = A  + (size_t)(rowBase + lr + 64) * D_ + lc * 8;
    const __half* Bga = Bt + (size_t)(colBase + lr) * D_ + lc * 8;
    const __half* Bgb = Bt + (size_t)(colBase + lr + 64) * D_ + lc * 8;
    const uint32_t sAa = sb + lr * 80 + lc * 16;
    const uint32_t sAb = sAa + 64 * 80;
    const uint32_t sBa = sb + 10240 + lr * 80 + lc * 16;
    const uint32_t sBb = sBa + 64 * 80;

    // ---- ldmatrix lane address bases ----
    // A: per mt (16-row blocks): lanes 0-15 rows, lanes 16-31 same rows +16B (k+8)
    const uint32_t aBase = sb + (uint32_t)((warpRow + (lane & 15)) * 80 + (lane >> 4) * 16);
    // B: pair p covers nt 2p,2p+1 (16 n-rows): lanes {0-7,16-23} row groups, bit3 -> k+8
    const uint32_t bBase = sb + 10240 +
        (uint32_t)((warpCol + (lane & 7) + ((lane >> 4) & 1) * 8) * 80 +
                   ((lane >> 3) & 1) * 16);

    float acc[4][4][4];
    #pragma unroll
    for (int i = 0; i < 4; i++)
        #pragma unroll
        for (int j = 0; j < 4; j++)
            #pragma unroll
            for (int r = 0; r < 4; r++) acc[i][j][r] = 0.f;

    const int NKT = D_ / 32;   // 32

    // ---- prologue: stages 0,1 ----
    #pragma unroll
    for (int s = 0; s < 2; s++) {
        uint32_t so = s * P3_STAGE;
        cp_async16(sAa + so, Aga + s * 32);
        cp_async16(sAb + so, Agb + s * 32);
        cp_async16(sBa + so, Bga + s * 32);
        cp_async16(sBb + so, Bgb + s * 32);
        CP_COMMIT();
    }

    int stage = 0;
    for (int kt = 0; kt < NKT; kt++) {
        if (kt >= NKT - 2) { CP_WAIT(0); } else { CP_WAIT(1); }
        __syncthreads();

        // issue stage kt+2 (buffer (kt+2)%3: its previous data was computed
        // at kt-1, completed by all warps before the sync above)
        if (kt + 2 < NKT) {
            int ns = (kt + 2) % 3;
            uint32_t so = ns * P3_STAGE;
            int ko = (kt + 2) * 32;
            cp_async16(sAa + so, Aga + ko);
            cp_async16(sAb + so, Agb + ko);
            cp_async16(sBa + so, Bga + ko);
            cp_async16(sBb + so, Bgb + ko);
            CP_COMMIT();
        }

        // ---- compute current stage ----
        const uint32_t so = stage * P3_STAGE;
        #pragma unroll
        for (int ks = 0; ks < 2; ks++) {
            uint32_t af[4][4], bp[2][4];
            #pragma unroll
            for (int mt = 0; mt < 4; mt++)
                ldsm_x4(af[mt], aBase + so + mt * (16 * 80) + ks * 32);
            #pragma unroll
            for (int p = 0; p < 2; p++)
                ldsm_x4(bp[p], bBase + so + p * (16 * 80) + ks * 32);
            #pragma unroll
            for (int mt = 0; mt < 4; mt++) {
                #pragma unroll
                for (int p = 0; p < 2; p++) {
                    uint32_t b0[2] = { bp[p][0], bp[p][1] };
                    uint32_t b1[2] = { bp[p][2], bp[p][3] };
                    mma_h(acc[mt][p * 2],     af[mt], b0);
                    mma_h(acc[mt][p * 2 + 1], af[mt], b1);
                }
            }
        }
        stage = (stage + 1) % 3;
        __syncthreads();
    }

    // ---- epilogue: bias + relu -> half2 stores ----
    const int g = lane >> 2;
    const int t = lane & 3;
    #pragma unroll
    for (int mt = 0; mt < 4; mt++) {
        int r = rowBase + warpRow + mt * 16 + g;
        #pragma unroll
        for (int nt = 0; nt < 4; nt++) {
            int c = colBase + warpCol + nt * 8 + 2 * t;
            float b0 = bvec[c], b1 = bvec[c + 1];
            uint32_t h0 = pack_h2(fmaxf(acc[mt][nt][0] + b0, 0.f),
                                  fmaxf(acc[mt][nt][1] + b1, 0.f));
            uint32_t h1 = pack_h2(fmaxf(acc[mt][nt][2] + b0, 0.f),
                                  fmaxf(acc[mt][nt][3] + b1, 0.f));
            *(uint32_t*)&C[(size_t)r * D_ + c]       = h0;
            *(uint32_t*)&C[(size_t)(r + 8) * D_ + c] = h1;
        }
    }
}

// ============================================================================
// scores: attn[b] = q_b @ k_b^T * scale + bias   -- fp16 mma
// ============================================================================
#define S_STAGE_W 5760
#define SCORES_SMEM (2 * S_STAGE_W * 4)

__global__ __launch_bounds__(288, 1)
void scores_h(const __half* __restrict__ q, const __half* __restrict__ k,
              const float* __restrict__ bias, float* __restrict__ attn,
              float scale)
{
    extern __shared__ uint32_t smu[];
    const uint32_t sb = smem_u32p(smu);

    const int b = blockIdx.x;
    const __half* qb = q + (size_t)b * S_ * D_;
    const __half* kb = k + (size_t)b * S_ * D_;

    const int tid  = threadIdx.x;
    const int lane = tid & 31;
    const int warp = tid >> 5;
    const int g = lane >> 2;
    const int t = lane & 3;
    const int warpRow = (warp / 3) * 48;
    const int warpCol = (warp % 3) * 48;

    const int r = tid >> 1;
    const int c0 = tid & 1;
    const __half* qg = qb + (size_t)r * D_;
    const __half* kg = kb + (size_t)r * D_;
    const uint32_t qSb = sb + r * 80;
    const uint32_t kSb = sb + 11520 + r * 80;

    float acc[3][6][4];
    #pragma unroll
    for (int i = 0; i < 3; i++)
        #pragma unroll
        for (int j = 0; j < 6; j++)
            #pragma unroll
            for (int rr = 0; rr < 4; rr++) acc[i][j][rr] = 0.f;

    const int NKT = D_ / 32;

    #pragma unroll
    for (int j = 0; j < 2; j++) {
        int ch = c0 + j * 2;
        cp_async16(qSb + ch * 16, qg + ch * 8);
        cp_async16(kSb + ch * 16, kg + ch * 8);
    }
    CP_COMMIT();

    for (int kt = 0; kt < NKT; kt++) {
        const int cur = kt & 1;
        if (kt + 1 < NKT) {
            const int nxt = cur ^ 1;
            #pragma unroll
            for (int j = 0; j < 2; j++) {
                int ch = c0 + j * 2;
                cp_async16(qSb + nxt * 23040 + ch * 16, qg + (kt + 1) * 32 + ch * 8);
                cp_async16(kSb + nxt * 23040 + ch * 16, kg + (kt + 1) * 32 + ch * 8);
            }
            CP_COMMIT();
            CP_WAIT(1);
        } else {
            CP_WAIT(0);
        }
        __syncthreads();

        const uint32_t* Qc = smu + cur * S_STAGE_W;
        const uint32_t* Kc = smu + cur * S_STAGE_W + 2880;
        #pragma unroll
        for (int ks = 0; ks < 2; ks++) {
            const int kd = ks * 8;
            uint32_t af[3][4], bf[6][2];
            #pragma unroll
            for (int mt = 0; mt < 3; mt++) {
                int m0 = warpRow + mt * 16;
                af[mt][0] = Qc[(m0 + g)     * 20 + kd + t];
                af[mt][1] = Qc[(m0 + g + 8) * 20 + kd + t];
                af[mt][2] = Qc[(m0 + g)     * 20 + kd + t + 4];
                af[mt][3] = Qc[(m0 + g + 8) * 20 + kd + t + 4];
            }
            #pragma unroll
            for (int nt = 0; nt < 6; nt++) {
                int n0 = warpCol + nt * 8;
                bf[nt][0] = Kc[(n0 + g) * 20 + kd + t];
                bf[nt][1] = Kc[(n0 + g) * 20 + kd + t + 4];
            }
            #pragma unroll
            for (int mt = 0; mt < 3; mt++)
                #pragma unroll
                for (int nt = 0; nt < 6; nt++)
                    mma_h(acc[mt][nt], af[mt], bf[nt]);
        }
        __syncthreads();
    }

    float* ab = attn + (size_t)b * S_ * S_;
    #pragma unroll
    for (int mt = 0; mt < 3; mt++) {
        int m = warpRow + mt * 16 + g;
        #pragma unroll
        for (int nt = 0; nt < 6; nt++) {
            int n = warpCol + nt * 8 + 2 * t;
            float2 bA = *(const float2*)&bias[m * S_ + n];
            float2 bB = *(const float2*)&bias[(m + 8) * S_ + n];
            float2 o0 = { fmaf(acc[mt][nt][0], scale, bA.x),
                          fmaf(acc[mt][nt][1], scale, bA.y) };
            float2 o1 = { fmaf(acc[mt][nt][2], scale, bB.x),
                          fmaf(acc[mt][nt][3], scale, bB.y) };
            *(float2*)&ab[(size_t)m * S_ + n]       = o0;
            *(float2*)&ab[(size_t)(m + 8) * S_ + n] = o1;
        }
    }
}

// ============================================================================
// softmax over rows of attn (fp32)
// ============================================================================
__global__ void softmax_kernel(float* __restrict__ attn)
{
    int warp = (blockIdx.x * blockDim.x + threadIdx.x) >> 5;
    int lane = threadIdx.x & 31;
    if (warp >= B_ * S_) return;
    float* row = attn + (size_t)warp * S_;

    float v[5];
    float mx = -INFINITY;
    #pragma unroll
    for (int i = 0; i < 5; i++) {
        int idx = lane + i * 32;
        v[i] = (idx < S_) ? row[idx] : -INFINITY;
        mx = fmaxf(mx, v[i]);
    }
    #pragma unroll
    for (int o = 16; o; o >>= 1) mx = fmaxf(mx, __shfl_xor_sync(0xffffffffu, mx, o));

    float s = 0.f;
    #pragma unroll
    for (int i = 0; i < 5; i++) {
        v[i] = __expf(v[i] - mx);
        s += v[i];
    }
    #pragma unroll
    for (int o = 16; o; o >>= 1) s += __shfl_xor_sync(0xffffffffu, s, o);

    float inv = 1.f / s;
    #pragma unroll
    for (int i = 0; i < 5; i++) {
        int idx = lane + i * 32;
        if (idx < S_) row[idx] = v[i] * inv;
    }
}

// ============================================================================
// out = attn @ v  -- fp16 mma
// ============================================================================
#define AV_SMEM ((144 * 28 + 128 * 28) * 4)

__global__ __launch_bounds__(384, 1)
void av_h(const float* __restrict__ attn, const __half* __restrict__ v,
          float* __restrict__ out)
{
    extern __shared__ uint32_t smu[];
    uint32_t* An = smu;
    uint32_t* Vs = smu + 144 * 28;

    const int b = blockIdx.y;
    const int colBase = blockIdx.x * 128;
    const float*  ab = attn + (size_t)b * S_ * S_;
    const __half* vb = v + (size_t)b * S_ * D_;

    const int tid  = threadIdx.x;
    const int lane = tid & 31;
    const int warp = tid >> 5;
    const int g = lane >> 2;
    const int t = lane & 3;
    const int warpRow = (warp >> 2) * 48;
    const int warpCol = (warp & 3) * 32;

    float acc[3][4][4];
    #pragma unroll
    for (int i = 0; i < 3; i++)
        #pragma unroll
        for (int j = 0; j < 4; j++)
            #pragma unroll
            for (int r = 0; r < 4; r++) acc[i][j][r] = 0.f;

    for (int k0 = 0; k0 < S_; k0 += 48) {
        for (int idx = tid; idx < 144 * 12; idx += 384) {
            int rr = idx / 12, cc = idx % 12;
            float4 x = *(const float4*)&ab[(size_t)rr * S_ + k0 + cc * 4];
            uint2 pp = { pack_h2(x.x, x.y), pack_h2(x.z, x.w) };
            *(uint2*)&An[rr * 28 + cc * 2] = pp;
        }
        unsigned short* vs16 = (unsigned short*)Vs;
        #pragma unroll
        for (int j = 0; j < 2; j++) {
            int idx = tid + j * 384;
            int tk = idx >> 4;
            int dch = idx & 15;
            uint4 u = *(const uint4*)&vb[(size_t)(k0 + tk) * D_ + colBase + dch * 8];
            const unsigned short* hs = (const unsigned short*)&u;
            #pragma unroll
            for (int e = 0; e < 8; e++)
                vs16[(dch * 8 + e) * 56 + tk] = hs[e];
        }
        __syncthreads();

        #pragma unroll
        for (int ks = 0; ks < 3; ks++) {
            const int kd = ks * 8;
            uint32_t af[3][4], bf[4][2];
            #pragma unroll
            for (int mt = 0; mt < 3; mt++) {
                int m0 = warpRow + mt * 16;
                af[mt][0] = An[(m0 + g)     * 28 + kd + t];
                af[mt][1] = An[(m0 + g + 8) * 28 + kd + t];
                af[mt][2] = An[(m0 + g)     * 28 + kd + t + 4];
                af[mt][3] = An[(m0 + g + 8) * 28 + kd + t + 4];
            }
            #pragma unroll
            for (int nt = 0; nt < 4; nt++) {
                int n0 = warpCol + nt * 8;
                bf[nt][0] = Vs[(n0 + g) * 28 + kd + t];
                bf[nt][1] = Vs[(n0 + g) * 28 + kd + t + 4];
            }
            #pragma unroll
            for (int mt = 0; mt < 3; mt++)
                #pragma unroll
                for (int nt = 0; nt < 4; nt++)
                    mma_h(acc[mt][nt], af[mt], bf[nt]);
        }
        __syncthreads();
    }

    #pragma unroll
    for (int mt = 0; mt < 3; mt++) {
        int m = warpRow + mt * 16 + g;
        #pragma unroll
        for (int nt = 0; nt < 4; nt++) {
            int n = colBase + warpCol + nt * 8 + 2 * t;
            float2 o0 = { acc[mt][nt][0], acc[mt][nt][1] };
            float2 o1 = { acc[mt][nt][2], acc[mt][nt][3] };
            *(float2*)&out[((size_t)b * S_ + m) * D_ + n]     = o0;
            *(float2*)&out[((size_t)b * S_ + m + 8) * D_ + n] = o1;
        }
    }
}

// ============================================================================
// launch
// ============================================================================
extern "C" void kernel_launch(void* const* d_in, const int* in_sizes, int n_in,
                              void* d_out, int out_size)
{
    const float* query = (const float*)d_in[0];
    const float* key   = (const float*)d_in[1];
    const float* value = (const float*)d_in[2];
    const float* Wq    = (const float*)d_in[3];
    const float* bq    = (const float*)d_in[4];
    const float* Wk    = (const float*)d_in[5];
    const float* bk    = (const float*)d_in[6];
    const float* Wv    = (const float*)d_in[7];
    const float* bv    = (const float*)d_in[8];
    const float* Wl    = (const float*)d_in[9];
    const float* bl    = (const float*)d_in[10];
    const float* wg    = (const float*)d_in[11];
    float* out = (float*)d_out;

    __half* ah;  cudaGetSymbolAddress((void**)&ah,  g_ah);
    __half* qh;  cudaGetSymbolAddress((void**)&qh,  g_q);
    __half* kh;  cudaGetSymbolAddress((void**)&kh,  g_k);
    __half* vh;  cudaGetSymbolAddress((void**)&vh,  g_v);
    __half* wt;  cudaGetSymbolAddress((void**)&wt,  g_wt);
    float* attn; cudaGetSymbolAddress((void**)&attn, g_attn);
    float* bias; cudaGetSymbolAddress((void**)&bias, g_bias);
    float* R;    cudaGetSymbolAddress((void**)&R,    g_R);
    float* T;    cudaGetSymbolAddress((void**)&T,    g_T);

    cudaFuncSetAttribute(proj_h2,
                         cudaFuncAttributeMaxDynamicSharedMemorySize, PROJ_SMEM);
    cudaFuncSetAttribute(scores_h,
                         cudaFuncAttributeMaxDynamicSharedMemorySize, SCORES_SMEM);
    cudaFuncSetAttribute(av_h,
                         cudaFuncAttributeMaxDynamicSharedMemorySize, AV_SMEM);

    // setup: input conversion, weight transpose, bias pipeline
    a2h<<<3 * BS_ * D_ / 8 / 256, 256>>>(query, key, value, ah);
    transpose_w<<<dim3(32, 32, 3), dim3(32, 8)>>>(Wq, Wk, Wv, wt);
    rel_kernel<<<144, 256>>>(Wl, bl, R);
    tgemm<<<dim3(3, 3), 256>>>(wg, R, T);
    scatter_bias<<<81, 256>>>(T, bias);

    // projections (fp16 HMMA, lean loop)
    proj_h2<<<dim3(8, 144, 3), 256, PROJ_SMEM>>>(ah, wt, bq, bk, bv, qh, kh, vh);

    // scores (+ scale + bias)
    float scale = 1.0f / sqrtf((float)D_);
    scores_h<<<B_, 288, SCORES_SMEM>>>(qh, kh, bias, attn, scale);

    // softmax
    int rows = B_ * S_;
    softmax_kernel<<<(rows * 32 + 255) / 256, 256>>>(attn);

    // out = attn @ v
    av_h<<<dim3(D_ / 128, B_), 384, AV_SMEM>>>(attn, vh, out);
}

// round 7
// speedup vs baseline: 5.6234x; 1.1563x over previous
#include <cuda_runtime.h>
#include <cuda_fp16.h>
#include <math.h>
#include <stdint.h>

// ============================================================================
// RegionAugmentedSelfAttention  (B=128, S=144, D=1024, GRID=12)
//   R7: fix tgemm launch-shape starvation (grid 9 -> 144 blocks, warp-dot).
//       Everything else = R6 (fp16 HMMA, cp.async+ldmatrix proj).
// ============================================================================

#define B_  128
#define S_  144
#define D_  1024
#define BS_ (B_ * S_)          // 18432

// -------- scratch (static device globals) -----------------------------------
__device__ __align__(16) unsigned short g_ah[3 * BS_ * D_];  // half q/k/v inputs
__device__ __align__(16) unsigned short g_q[BS_ * D_];
__device__ __align__(16) unsigned short g_k[BS_ * D_];
__device__ __align__(16) unsigned short g_v[BS_ * D_];
__device__ __align__(16) unsigned short g_wt[3 * D_ * D_];   // half W^T (n,k)
__device__ float g_attn[B_ * S_ * S_];
__device__ float g_bias[S_ * S_];
__device__ float g_R[144 * D_];
__device__ float g_T[S_ * S_];

// ---------------------------------------------------------------------------
// helpers
// ---------------------------------------------------------------------------
__device__ __forceinline__ uint32_t pack_h2(float lo, float hi) {
    uint32_t r;
    asm("cvt.rn.f16x2.f32 %0, %1, %2;" : "=r"(r) : "f"(hi), "f"(lo));
    return r;
}

__device__ __forceinline__ void mma_h(float (&d)[4],
                                      const uint32_t (&a)[4],
                                      const uint32_t (&b)[2]) {
    asm volatile(
        "mma.sync.aligned.m16n8k16.row.col.f32.f16.f16.f32 "
        "{%0,%1,%2,%3}, {%4,%5,%6,%7}, {%8,%9}, {%0,%1,%2,%3};\n"
        : "+f"(d[0]), "+f"(d[1]), "+f"(d[2]), "+f"(d[3])
        : "r"(a[0]), "r"(a[1]), "r"(a[2]), "r"(a[3]),
          "r"(b[0]), "r"(b[1]));
}

__device__ __forceinline__ void ldsm_x4(uint32_t (&r)[4], uint32_t addr) {
    asm volatile("ldmatrix.sync.aligned.m8n8.x4.shared.b16 {%0,%1,%2,%3}, [%4];"
                 : "=r"(r[0]), "=r"(r[1]), "=r"(r[2]), "=r"(r[3]) : "r"(addr));
}

__device__ __forceinline__ void cp_async16(uint32_t smem_addr, const void* gptr) {
    asm volatile("cp.async.cg.shared.global [%0], [%1], 16;\n"
                 :: "r"(smem_addr), "l"(gptr));
}
#define CP_COMMIT()  asm volatile("cp.async.commit_group;\n")
#define CP_WAIT(N)   asm volatile("cp.async.wait_group %0;\n" :: "n"(N))

__device__ __forceinline__ uint32_t smem_u32p(const void* p) {
    return (uint32_t)__cvta_generic_to_shared(p);
}

// ============================================================================
// input fp32 -> fp16 (8 elems / thread)
// ============================================================================
__global__ void a2h(const float* __restrict__ q, const float* __restrict__ k,
                    const float* __restrict__ v, __half* __restrict__ out)
{
    const size_t per = (size_t)BS_ * D_ / 8;
    size_t i = (size_t)blockIdx.x * 256 + threadIdx.x;
    const float* src;
    size_t off;
    if (i < per)           { src = q; off = i; }
    else if (i < 2 * per)  { src = k; off = i - per; }
    else                   { src = v; off = i - 2 * per; }
    float4 x0 = ((const float4*)src)[off * 2];
    float4 x1 = ((const float4*)src)[off * 2 + 1];
    uint4 u = { pack_h2(x0.x, x0.y), pack_h2(x0.z, x0.w),
                pack_h2(x1.x, x1.y), pack_h2(x1.z, x1.w) };
    ((uint4*)out)[i] = u;
}

// ============================================================================
// Bias pipeline (batch-independent)
// ============================================================================
__global__ void rel_kernel(const float* __restrict__ Wl,
                           const float* __restrict__ bl,
                           float* __restrict__ R)
{
    int c = blockIdx.x;
    int a = c / 12, b = c % 12;
    float dx = logf(fmaxf((float)a * 0.5f, 1e-10f));
    float dy = logf(fmaxf((float)b * 0.5f, 1e-10f));
    for (int d = threadIdx.x; d < D_; d += blockDim.x)
        R[c * D_ + d] = fmaxf(fmaf(dx, Wl[d], fmaf(dy, Wl[D_ + d], bl[d])), 0.f);
}

// T[i][c] = dot(wg[i], R[c])  -- one block per i, warp per c, shuffle reduce
__global__ __launch_bounds__(256)
void tgemm2(const float* __restrict__ wg, const float* __restrict__ R,
            float* __restrict__ T)
{
    __shared__ float w[D_];
    const int i = blockIdx.x;
    for (int d = threadIdx.x * 4; d < D_; d += 1024)
        *(float4*)&w[d] = *(const float4*)&wg[(size_t)i * D_ + d];
    __syncthreads();

    const int warp = threadIdx.x >> 5;
    const int lane = threadIdx.x & 31;
    for (int c = warp; c < S_; c += 8) {
        const float* Rc = R + (size_t)c * D_;
        float s = 0.f;
        #pragma unroll
        for (int d = lane * 4; d < D_; d += 128) {
            float4 r4 = *(const float4*)&Rc[d];
            s += r4.x * w[d] + r4.y * w[d + 1] + r4.z * w[d + 2] + r4.w * w[d + 3];
        }
        #pragma unroll
        for (int o = 16; o; o >>= 1) s += __shfl_xor_sync(0xffffffffu, s, o);
        if (lane == 0) T[i * S_ + c] = s;
    }
}

__global__ void scatter_bias(const float* __restrict__ T, float* __restrict__ bias)
{
    int idx = blockIdx.x * 256 + threadIdx.x;
    if (idx >= S_ * S_) return;
    int i = idx / S_, j = idx % S_;
    int dr = abs(i / 12 - j / 12);
    int dc = abs(i % 12 - j % 12);
    bias[idx] = fmaxf(T[i * S_ + dr * 12 + dc], 0.f);
}

// ============================================================================
// transpose + convert weights:  Wt[z][n][k] = half(W_z[k][n])
// ============================================================================
__global__ void transpose_w(const float* __restrict__ Wq,
                            const float* __restrict__ Wk,
                            const float* __restrict__ Wv,
                            __half* __restrict__ Wt)
{
    __shared__ float t[32][33];
    const float* W = (blockIdx.z == 0) ? Wq : (blockIdx.z == 1) ? Wk : Wv;
    __half* O = Wt + (size_t)blockIdx.z * D_ * D_;
    int x0 = blockIdx.x * 32, y0 = blockIdx.y * 32;
    #pragma unroll
    for (int r = threadIdx.y; r < 32; r += 8)
        t[r][threadIdx.x] = W[(size_t)(y0 + r) * D_ + x0 + threadIdx.x];
    __syncthreads();
    #pragma unroll
    for (int r = threadIdx.y; r < 32; r += 8)
        O[(size_t)(x0 + r) * D_ + y0 + threadIdx.x] = __float2half(t[threadIdx.x][r]);
}

// ============================================================================
// Projection GEMM  C = relu(A @ W + b)  -- fp16 HMMA, lean inner loop
// ============================================================================
#define P3_STAGE 20480
#define PROJ_SMEM (3 * P3_STAGE)        // 61440 B

__global__ __launch_bounds__(256, 2)
void proj_h2(const __half* __restrict__ Ah, const __half* __restrict__ Wt,
             const float* __restrict__ bq, const float* __restrict__ bk,
             const float* __restrict__ bv,
             __half* __restrict__ Cq, __half* __restrict__ Ck,
             __half* __restrict__ Cv)
{
    extern __shared__ char smc[];
    const uint32_t sb = smem_u32p(smc);

    const int z = blockIdx.z;
    const __half* A  = Ah + (size_t)z * BS_ * D_;
    const __half* Bt = Wt + (size_t)z * D_ * D_;
    const float* bvec = (z == 0) ? bq : (z == 1) ? bk : bv;
    __half* C = (z == 0) ? Cq : (z == 1) ? Ck : Cv;

    const int tid  = threadIdx.x;
    const int lane = tid & 31;
    const int warp = tid >> 5;
    const int rowBase = blockIdx.y * 128;
    const int colBase = blockIdx.x * 128;
    const int warpRow = (warp >> 2) * 64;
    const int warpCol = (warp & 3) * 32;

    const int lr = tid >> 2;
    const int lc = tid & 3;
    const __half* Aga = A  + (size_t)(rowBase + lr) * D_ + lc * 8;
    const __half* Agb = A  + (size_t)(rowBase + lr + 64) * D_ + lc * 8;
    const __half* Bga = Bt + (size_t)(colBase + lr) * D_ + lc * 8;
    const __half* Bgb = Bt + (size_t)(colBase + lr + 64) * D_ + lc * 8;
    const uint32_t sAa = sb + lr * 80 + lc * 16;
    const uint32_t sAb = sAa + 64 * 80;
    const uint32_t sBa = sb + 10240 + lr * 80 + lc * 16;
    const uint32_t sBb = sBa + 64 * 80;

    const uint32_t aBase = sb + (uint32_t)((warpRow + (lane & 15)) * 80 + (lane >> 4) * 16);
    const uint32_t bBase = sb + 10240 +
        (uint32_t)((warpCol + (lane & 7) + ((lane >> 4) & 1) * 8) * 80 +
                   ((lane >> 3) & 1) * 16);

    float acc[4][4][4];
    #pragma unroll
    for (int i = 0; i < 4; i++)
        #pragma unroll
        for (int j = 0; j < 4; j++)
            #pragma unroll
            for (int r = 0; r < 4; r++) acc[i][j][r] = 0.f;

    const int NKT = D_ / 32;

    #pragma unroll
    for (int s = 0; s < 2; s++) {
        uint32_t so = s * P3_STAGE;
        cp_async16(sAa + so, Aga + s * 32);
        cp_async16(sAb + so, Agb + s * 32);
        cp_async16(sBa + so, Bga + s * 32);
        cp_async16(sBb + so, Bgb + s * 32);
        CP_COMMIT();
    }

    int stage = 0;
    for (int kt = 0; kt < NKT; kt++) {
        if (kt >= NKT - 2) { CP_WAIT(0); } else { CP_WAIT(1); }
        __syncthreads();

        if (kt + 2 < NKT) {
            int ns = (kt + 2) % 3;
            uint32_t so = ns * P3_STAGE;
            int ko = (kt + 2) * 32;
            cp_async16(sAa + so, Aga + ko);
            cp_async16(sAb + so, Agb + ko);
            cp_async16(sBa + so, Bga + ko);
            cp_async16(sBb + so, Bgb + ko);
            CP_COMMIT();
        }

        const uint32_t so = stage * P3_STAGE;
        #pragma unroll
        for (int ks = 0; ks < 2; ks++) {
            uint32_t af[4][4], bp[2][4];
            #pragma unroll
            for (int mt = 0; mt < 4; mt++)
                ldsm_x4(af[mt], aBase + so + mt * (16 * 80) + ks * 32);
            #pragma unroll
            for (int p = 0; p < 2; p++)
                ldsm_x4(bp[p], bBase + so + p * (16 * 80) + ks * 32);
            #pragma unroll
            for (int mt = 0; mt < 4; mt++) {
                #pragma unroll
                for (int p = 0; p < 2; p++) {
                    uint32_t b0[2] = { bp[p][0], bp[p][1] };
                    uint32_t b1[2] = { bp[p][2], bp[p][3] };
                    mma_h(acc[mt][p * 2],     af[mt], b0);
                    mma_h(acc[mt][p * 2 + 1], af[mt], b1);
                }
            }
        }
        stage = (stage + 1) % 3;
        __syncthreads();
    }

    const int g = lane >> 2;
    const int t = lane & 3;
    #pragma unroll
    for (int mt = 0; mt < 4; mt++) {
        int r = rowBase + warpRow + mt * 16 + g;
        #pragma unroll
        for (int nt = 0; nt < 4; nt++) {
            int c = colBase + warpCol + nt * 8 + 2 * t;
            float b0 = bvec[c], b1 = bvec[c + 1];
            uint32_t h0 = pack_h2(fmaxf(acc[mt][nt][0] + b0, 0.f),
                                  fmaxf(acc[mt][nt][1] + b1, 0.f));
            uint32_t h1 = pack_h2(fmaxf(acc[mt][nt][2] + b0, 0.f),
                                  fmaxf(acc[mt][nt][3] + b1, 0.f));
            *(uint32_t*)&C[(size_t)r * D_ + c]       = h0;
            *(uint32_t*)&C[(size_t)(r + 8) * D_ + c] = h1;
        }
    }
}

// ============================================================================
// scores: attn[b] = q_b @ k_b^T * scale + bias   -- fp16 mma
// ============================================================================
#define S_STAGE_W 5760
#define SCORES_SMEM (2 * S_STAGE_W * 4)

__global__ __launch_bounds__(288, 1)
void scores_h(const __half* __restrict__ q, const __half* __restrict__ k,
              const float* __restrict__ bias, float* __restrict__ attn,
              float scale)
{
    extern __shared__ uint32_t smu[];
    const uint32_t sb = smem_u32p(smu);

    const int b = blockIdx.x;
    const __half* qb = q + (size_t)b * S_ * D_;
    const __half* kb = k + (size_t)b * S_ * D_;

    const int tid  = threadIdx.x;
    const int lane = tid & 31;
    const int warp = tid >> 5;
    const int g = lane >> 2;
    const int t = lane & 3;
    const int warpRow = (warp / 3) * 48;
    const int warpCol = (warp % 3) * 48;

    const int r = tid >> 1;
    const int c0 = tid & 1;
    const __half* qg = qb + (size_t)r * D_;
    const __half* kg = kb + (size_t)r * D_;
    const uint32_t qSb = sb + r * 80;
    const uint32_t kSb = sb + 11520 + r * 80;

    float acc[3][6][4];
    #pragma unroll
    for (int i = 0; i < 3; i++)
        #pragma unroll
        for (int j = 0; j < 6; j++)
            #pragma unroll
            for (int rr = 0; rr < 4; rr++) acc[i][j][rr] = 0.f;

    const int NKT = D_ / 32;

    #pragma unroll
    for (int j = 0; j < 2; j++) {
        int ch = c0 + j * 2;
        cp_async16(qSb + ch * 16, qg + ch * 8);
        cp_async16(kSb + ch * 16, kg + ch * 8);
    }
    CP_COMMIT();

    for (int kt = 0; kt < NKT; kt++) {
        const int cur = kt & 1;
        if (kt + 1 < NKT) {
            const int nxt = cur ^ 1;
            #pragma unroll
            for (int j = 0; j < 2; j++) {
                int ch = c0 + j * 2;
                cp_async16(qSb + nxt * 23040 + ch * 16, qg + (kt + 1) * 32 + ch * 8);
                cp_async16(kSb + nxt * 23040 + ch * 16, kg + (kt + 1) * 32 + ch * 8);
            }
            CP_COMMIT();
            CP_WAIT(1);
        } else {
            CP_WAIT(0);
        }
        __syncthreads();

        const uint32_t* Qc = smu + cur * S_STAGE_W;
        const uint32_t* Kc = smu + cur * S_STAGE_W + 2880;
        #pragma unroll
        for (int ks = 0; ks < 2; ks++) {
            const int kd = ks * 8;
            uint32_t af[3][4], bf[6][2];
            #pragma unroll
            for (int mt = 0; mt < 3; mt++) {
                int m0 = warpRow + mt * 16;
                af[mt][0] = Qc[(m0 + g)     * 20 + kd + t];
                af[mt][1] = Qc[(m0 + g + 8) * 20 + kd + t];
                af[mt][2] = Qc[(m0 + g)     * 20 + kd + t + 4];
                af[mt][3] = Qc[(m0 + g + 8) * 20 + kd + t + 4];
            }
            #pragma unroll
            for (int nt = 0; nt < 6; nt++) {
                int n0 = warpCol + nt * 8;
                bf[nt][0] = Kc[(n0 + g) * 20 + kd + t];
                bf[nt][1] = Kc[(n0 + g) * 20 + kd + t + 4];
            }
            #pragma unroll
            for (int mt = 0; mt < 3; mt++)
                #pragma unroll
                for (int nt = 0; nt < 6; nt++)
                    mma_h(acc[mt][nt], af[mt], bf[nt]);
        }
        __syncthreads();
    }

    float* ab = attn + (size_t)b * S_ * S_;
    #pragma unroll
    for (int mt = 0; mt < 3; mt++) {
        int m = warpRow + mt * 16 + g;
        #pragma unroll
        for (int nt = 0; nt < 6; nt++) {
            int n = warpCol + nt * 8 + 2 * t;
            float2 bA = *(const float2*)&bias[m * S_ + n];
            float2 bB = *(const float2*)&bias[(m + 8) * S_ + n];
            float2 o0 = { fmaf(acc[mt][nt][0], scale, bA.x),
                          fmaf(acc[mt][nt][1], scale, bA.y) };
            float2 o1 = { fmaf(acc[mt][nt][2], scale, bB.x),
                          fmaf(acc[mt][nt][3], scale, bB.y) };
            *(float2*)&ab[(size_t)m * S_ + n]       = o0;
            *(float2*)&ab[(size_t)(m + 8) * S_ + n] = o1;
        }
    }
}

// ============================================================================
// softmax over rows of attn (fp32)
// ============================================================================
__global__ void softmax_kernel(float* __restrict__ attn)
{
    int warp = (blockIdx.x * blockDim.x + threadIdx.x) >> 5;
    int lane = threadIdx.x & 31;
    if (warp >= B_ * S_) return;
    float* row = attn + (size_t)warp * S_;

    float v[5];
    float mx = -INFINITY;
    #pragma unroll
    for (int i = 0; i < 5; i++) {
        int idx = lane + i * 32;
        v[i] = (idx < S_) ? row[idx] : -INFINITY;
        mx = fmaxf(mx, v[i]);
    }
    #pragma unroll
    for (int o = 16; o; o >>= 1) mx = fmaxf(mx, __shfl_xor_sync(0xffffffffu, mx, o));

    float s = 0.f;
    #pragma unroll
    for (int i = 0; i < 5; i++) {
        v[i] = __expf(v[i] - mx);
        s += v[i];
    }
    #pragma unroll
    for (int o = 16; o; o >>= 1) s += __shfl_xor_sync(0xffffffffu, s, o);

    float inv = 1.f / s;
    #pragma unroll
    for (int i = 0; i < 5; i++) {
        int idx = lane + i * 32;
        if (idx < S_) row[idx] = v[i] * inv;
    }
}

// ============================================================================
// out = attn @ v  -- fp16 mma
// ============================================================================
#define AV_SMEM ((144 * 28 + 128 * 28) * 4)

__global__ __launch_bounds__(384, 1)
void av_h(const float* __restrict__ attn, const __half* __restrict__ v,
          float* __restrict__ out)
{
    extern __shared__ uint32_t smu[];
    uint32_t* An = smu;
    uint32_t* Vs = smu + 144 * 28;

    const int b = blockIdx.y;
    const int colBase = blockIdx.x * 128;
    const float*  ab = attn + (size_t)b * S_ * S_;
    const __half* vb = v + (size_t)b * S_ * D_;

    const int tid  = threadIdx.x;
    const int lane = tid & 31;
    const int warp = tid >> 5;
    const int g = lane >> 2;
    const int t = lane & 3;
    const int warpRow = (warp >> 2) * 48;
    const int warpCol = (warp & 3) * 32;

    float acc[3][4][4];
    #pragma unroll
    for (int i = 0; i < 3; i++)
        #pragma unroll
        for (int j = 0; j < 4; j++)
            #pragma unroll
            for (int r = 0; r < 4; r++) acc[i][j][r] = 0.f;

    for (int k0 = 0; k0 < S_; k0 += 48) {
        for (int idx = tid; idx < 144 * 12; idx += 384) {
            int rr = idx / 12, cc = idx % 12;
            float4 x = *(const float4*)&ab[(size_t)rr * S_ + k0 + cc * 4];
            uint2 pp = { pack_h2(x.x, x.y), pack_h2(x.z, x.w) };
            *(uint2*)&An[rr * 28 + cc * 2] = pp;
        }
        unsigned short* vs16 = (unsigned short*)Vs;
        #pragma unroll
        for (int j = 0; j < 2; j++) {
            int idx = tid + j * 384;
            int tk = idx >> 4;
            int dch = idx & 15;
            uint4 u = *(const uint4*)&vb[(size_t)(k0 + tk) * D_ + colBase + dch * 8];
            const unsigned short* hs = (const unsigned short*)&u;
            #pragma unroll
            for (int e = 0; e < 8; e++)
                vs16[(dch * 8 + e) * 56 + tk] = hs[e];
        }
        __syncthreads();

        #pragma unroll
        for (int ks = 0; ks < 3; ks++) {
            const int kd = ks * 8;
            uint32_t af[3][4], bf[4][2];
            #pragma unroll
            for (int mt = 0; mt < 3; mt++) {
                int m0 = warpRow + mt * 16;
                af[mt][0] = An[(m0 + g)     * 28 + kd + t];
                af[mt][1] = An[(m0 + g + 8) * 28 + kd + t];
                af[mt][2] = An[(m0 + g)     * 28 + kd + t + 4];
                af[mt][3] = An[(m0 + g + 8) * 28 + kd + t + 4];
            }
            #pragma unroll
            for (int nt = 0; nt < 4; nt++) {
                int n0 = warpCol + nt * 8;
                bf[nt][0] = Vs[(n0 + g) * 28 + kd + t];
                bf[nt][1] = Vs[(n0 + g) * 28 + kd + t + 4];
            }
            #pragma unroll
            for (int mt = 0; mt < 3; mt++)
                #pragma unroll
                for (int nt = 0; nt < 4; nt++)
                    mma_h(acc[mt][nt], af[mt], bf[nt]);
        }
        __syncthreads();
    }

    #pragma unroll
    for (int mt = 0; mt < 3; mt++) {
        int m = warpRow + mt * 16 + g;
        #pragma unroll
        for (int nt = 0; nt < 4; nt++) {
            int n = colBase + warpCol + nt * 8 + 2 * t;
            float2 o0 = { acc[mt][nt][0], acc[mt][nt][1] };
            float2 o1 = { acc[mt][nt][2], acc[mt][nt][3] };
            *(float2*)&out[((size_t)b * S_ + m) * D_ + n]     = o0;
            *(float2*)&out[((size_t)b * S_ + m + 8) * D_ + n] = o1;
        }
    }
}

// ============================================================================
// launch
// ============================================================================
extern "C" void kernel_launch(void* const* d_in, const int* in_sizes, int n_in,
                              void* d_out, int out_size)
{
    const float* query = (const float*)d_in[0];
    const float* key   = (const float*)d_in[1];
    const float* value = (const float*)d_in[2];
    const float* Wq    = (const float*)d_in[3];
    const float* bq    = (const float*)d_in[4];
    const float* Wk    = (const float*)d_in[5];
    const float* bk    = (const float*)d_in[6];
    const float* Wv    = (const float*)d_in[7];
    const float* bv    = (const float*)d_in[8];
    const float* Wl    = (const float*)d_in[9];
    const float* bl    = (const float*)d_in[10];
    const float* wg    = (const float*)d_in[11];
    float* out = (float*)d_out;

    __half* ah;  cudaGetSymbolAddress((void**)&ah,  g_ah);
    __half* qh;  cudaGetSymbolAddress((void**)&qh,  g_q);
    __half* kh;  cudaGetSymbolAddress((void**)&kh,  g_k);
    __half* vh;  cudaGetSymbolAddress((void**)&vh,  g_v);
    __half* wt;  cudaGetSymbolAddress((void**)&wt,  g_wt);
    float* attn; cudaGetSymbolAddress((void**)&attn, g_attn);
    float* bias; cudaGetSymbolAddress((void**)&bias, g_bias);
    float* R;    cudaGetSymbolAddress((void**)&R,    g_R);
    float* T;    cudaGetSymbolAddress((void**)&T,    g_T);

    cudaFuncSetAttribute(proj_h2,
                         cudaFuncAttributeMaxDynamicSharedMemorySize, PROJ_SMEM);
    cudaFuncSetAttribute(scores_h,
                         cudaFuncAttributeMaxDynamicSharedMemorySize, SCORES_SMEM);
    cudaFuncSetAttribute(av_h,
                         cudaFuncAttributeMaxDynamicSharedMemorySize, AV_SMEM);

    // setup: input conversion, weight transpose, bias pipeline
    a2h<<<3 * BS_ * D_ / 8 / 256, 256>>>(query, key, value, ah);
    transpose_w<<<dim3(32, 32, 3), dim3(32, 8)>>>(Wq, Wk, Wv, wt);
    rel_kernel<<<144, 256>>>(Wl, bl, R);
    tgemm2<<<144, 256>>>(wg, R, T);
    scatter_bias<<<81, 256>>>(T, bias);

    // projections (fp16 HMMA)
    proj_h2<<<dim3(8, 144, 3), 256, PROJ_SMEM>>>(ah, wt, bq, bk, bv, qh, kh, vh);

    // scores (+ scale + bias)
    float scale = 1.0f / sqrtf((float)D_);
    scores_h<<<B_, 288, SCORES_SMEM>>>(qh, kh, bias, attn, scale);

    // softmax
    int rows = B_ * S_;
    softmax_kernel<<<(rows * 32 + 255) / 256, 256>>>(attn);

    // out = attn @ v
    av_h<<<dim3(D_ / 128, B_), 384, AV_SMEM>>>(attn, vh, out);
}

// round 9
// speedup vs baseline: 5.9146x; 1.0518x over previous
#include <cuda_runtime.h>
#include <cuda_fp16.h>
#include <math.h>
#include <stdint.h>

// ============================================================================
// RegionAugmentedSelfAttention  (B=128, S=144, D=1024, GRID=12)
//   R9: R8 with the setup_fused block-partition bug fixed
//       (a2h needs 27648 blocks, not 9216).
// ============================================================================

#define B_  128
#define S_  144
#define D_  1024
#define BS_ (B_ * S_)          // 18432

// -------- scratch (static device globals) -----------------------------------
__device__ __align__(16) unsigned short g_ah[3 * BS_ * D_];  // half q/k/v inputs
__device__ __align__(16) unsigned short g_q[BS_ * D_];
__device__ __align__(16) unsigned short g_k[BS_ * D_];
__device__ __align__(16) unsigned short g_v[BS_ * D_];
__device__ __align__(16) unsigned short g_wt[3 * D_ * D_];   // half W^T (n,k)
__device__ __align__(16) unsigned short g_attn_h[B_ * S_ * S_]; // half attn
__device__ float g_bias[S_ * S_];
__device__ float g_R[144 * D_];

// ---------------------------------------------------------------------------
// helpers
// ---------------------------------------------------------------------------
__device__ __forceinline__ uint32_t pack_h2(float lo, float hi) {
    uint32_t r;
    asm("cvt.rn.f16x2.f32 %0, %1, %2;" : "=r"(r) : "f"(hi), "f"(lo));
    return r;
}

__device__ __forceinline__ void mma_h(float (&d)[4],
                                      const uint32_t (&a)[4],
                                      const uint32_t (&b)[2]) {
    asm volatile(
        "mma.sync.aligned.m16n8k16.row.col.f32.f16.f16.f32 "
        "{%0,%1,%2,%3}, {%4,%5,%6,%7}, {%8,%9}, {%0,%1,%2,%3};\n"
        : "+f"(d[0]), "+f"(d[1]), "+f"(d[2]), "+f"(d[3])
        : "r"(a[0]), "r"(a[1]), "r"(a[2]), "r"(a[3]),
          "r"(b[0]), "r"(b[1]));
}

__device__ __forceinline__ void ldsm_x4(uint32_t (&r)[4], uint32_t addr) {
    asm volatile("ldmatrix.sync.aligned.m8n8.x4.shared.b16 {%0,%1,%2,%3}, [%4];"
                 : "=r"(r[0]), "=r"(r[1]), "=r"(r[2]), "=r"(r[3]) : "r"(addr));
}

__device__ __forceinline__ void cp_async16(uint32_t smem_addr, const void* gptr) {
    asm volatile("cp.async.cg.shared.global [%0], [%1], 16;\n"
                 :: "r"(smem_addr), "l"(gptr));
}
#define CP_COMMIT()  asm volatile("cp.async.commit_group;\n")
#define CP_WAIT(N)   asm volatile("cp.async.wait_group %0;\n" :: "n"(N))

__device__ __forceinline__ uint32_t smem_u32p(const void* p) {
    return (uint32_t)__cvta_generic_to_shared(p);
}

// ============================================================================
// Fused setup: blocks [0,27648) a2h | [27648,30720) transpose_w |
//              [30720,30864) rel
// ============================================================================
#define SETUP_A2H_BLOCKS   27648      // 3*BS_*D_/8/256
#define SETUP_TRANS_BLOCKS 3072       // 3 * 32 * 32
#define SETUP_REL_BLOCKS   144
#define SETUP_BLOCKS (SETUP_A2H_BLOCKS + SETUP_TRANS_BLOCKS + SETUP_REL_BLOCKS)

__global__ __launch_bounds__(256)
void setup_fused(const float* __restrict__ q, const float* __restrict__ k,
                 const float* __restrict__ v, __half* __restrict__ ah,
                 const float* __restrict__ Wq, const float* __restrict__ Wk,
                 const float* __restrict__ Wv, __half* __restrict__ Wt,
                 const float* __restrict__ Wl, const float* __restrict__ bl,
                 float* __restrict__ R)
{
    __shared__ float t[32][33];
    const int bid = blockIdx.x;
    const int tid = threadIdx.x;

    if (bid < SETUP_A2H_BLOCKS) {
        // ---- a2h: fp32 -> fp16, 8 elems/thread ----
        const size_t per = (size_t)BS_ * D_ / 8;
        size_t i = (size_t)bid * 256 + tid;
        const float* src;
        size_t off;
        if (i < per)           { src = q; off = i; }
        else if (i < 2 * per)  { src = k; off = i - per; }
        else                   { src = v; off = i - 2 * per; }
        float4 x0 = ((const float4*)src)[off * 2];
        float4 x1 = ((const float4*)src)[off * 2 + 1];
        uint4 u = { pack_h2(x0.x, x0.y), pack_h2(x0.z, x0.w),
                    pack_h2(x1.x, x1.y), pack_h2(x1.z, x1.w) };
        ((uint4*)ah)[i] = u;
    } else if (bid < SETUP_A2H_BLOCKS + SETUP_TRANS_BLOCKS) {
        // ---- transpose_w: Wt[z][n][k] = half(W_z[k][n]) ----
        int b2 = bid - SETUP_A2H_BLOCKS;
        int z = b2 >> 10;
        int rem = b2 & 1023;
        int bx = rem & 31, by = rem >> 5;
        const float* W = (z == 0) ? Wq : (z == 1) ? Wk : Wv;
        __half* O = Wt + (size_t)z * D_ * D_;
        int x0 = bx * 32, y0 = by * 32;
        int tx = tid & 31, ty = tid >> 5;
        #pragma unroll
        for (int r = ty; r < 32; r += 8)
            t[r][tx] = W[(size_t)(y0 + r) * D_ + x0 + tx];
        __syncthreads();
        #pragma unroll
        for (int r = ty; r < 32; r += 8)
            O[(size_t)(x0 + r) * D_ + y0 + tx] = __float2half(t[tx][r]);
    } else {
        // ---- rel: R[c][d] = relu(dx*Wl0[d] + dy*Wl1[d] + bl[d]) ----
        int c = bid - (SETUP_A2H_BLOCKS + SETUP_TRANS_BLOCKS);
        int a = c / 12, b = c % 12;
        float dx = logf(fmaxf((float)a * 0.5f, 1e-10f));
        float dy = logf(fmaxf((float)b * 0.5f, 1e-10f));
        for (int d = tid; d < D_; d += 256)
            R[c * D_ + d] = fmaxf(fmaf(dx, Wl[d], fmaf(dy, Wl[D_ + d], bl[d])), 0.f);
    }
}

// ============================================================================
// tgemm + bias scatter fused.  grid (144 rows, 4 quarters).
// ============================================================================
__global__ __launch_bounds__(256)
void tgemm_bias(const float* __restrict__ wg, const float* __restrict__ R,
                float* __restrict__ bias)
{
    __shared__ float w[D_];
    __shared__ float Tp[36];
    const int i = blockIdx.x;
    const int qt = blockIdx.y;
    const int tid = threadIdx.x;

    *(float4*)&w[tid * 4] = *(const float4*)&wg[(size_t)i * D_ + tid * 4];
    __syncthreads();

    const int warp = tid >> 5;
    const int lane = tid & 31;
    for (int cl = warp; cl < 36; cl += 8) {
        const float* Rc = R + (size_t)(qt * 36 + cl) * D_;
        float s = 0.f;
        #pragma unroll
        for (int d = lane * 4; d < D_; d += 128) {
            float4 r4 = *(const float4*)&Rc[d];
            s += r4.x * w[d] + r4.y * w[d + 1] + r4.z * w[d + 2] + r4.w * w[d + 3];
        }
        #pragma unroll
        for (int o = 16; o; o >>= 1) s += __shfl_xor_sync(0xffffffffu, s, o);
        if (lane == 0) Tp[cl] = s;
    }
    __syncthreads();

    const int base = qt * 36;
    for (int j = tid; j < S_; j += 256) {
        int dr = abs(i / 12 - j / 12);
        int dc = abs(i % 12 - j % 12);
        int combo = dr * 12 + dc;
        if (combo >= base && combo < base + 36)
            bias[i * S_ + j] = fmaxf(Tp[combo - base], 0.f);
    }
}

// ============================================================================
// Projection GEMM  C = relu(A @ W + b)  -- fp16 HMMA
// ============================================================================
#define P3_STAGE 20480
#define PROJ_SMEM (3 * P3_STAGE)        // 61440 B

__global__ __launch_bounds__(256, 2)
void proj_h2(const __half* __restrict__ Ah, const __half* __restrict__ Wt,
             const float* __restrict__ bq, const float* __restrict__ bk,
             const float* __restrict__ bv,
             __half* __restrict__ Cq, __half* __restrict__ Ck,
             __half* __restrict__ Cv)
{
    extern __shared__ char smc[];
    const uint32_t sb = smem_u32p(smc);

    const int z = blockIdx.z;
    const __half* A  = Ah + (size_t)z * BS_ * D_;
    const __half* Bt = Wt + (size_t)z * D_ * D_;
    const float* bvec = (z == 0) ? bq : (z == 1) ? bk : bv;
    __half* C = (z == 0) ? Cq : (z == 1) ? Ck : Cv;

    const int tid  = threadIdx.x;
    const int lane = tid & 31;
    const int warp = tid >> 5;
    const int rowBase = blockIdx.y * 128;
    const int colBase = blockIdx.x * 128;
    const int warpRow = (warp >> 2) * 64;
    const int warpCol = (warp & 3) * 32;

    const int lr = tid >> 2;
    const int lc = tid & 3;
    const __half* Aga = A  + (size_t)(rowBase + lr) * D_ + lc * 8;
    const __half* Agb = A  + (size_t)(rowBase + lr + 64) * D_ + lc * 8;
    const __half* Bga = Bt + (size_t)(colBase + lr) * D_ + lc * 8;
    const __half* Bgb = Bt + (size_t)(colBase + lr + 64) * D_ + lc * 8;
    const uint32_t sAa = sb + lr * 80 + lc * 16;
    const uint32_t sAb = sAa + 64 * 80;
    const uint32_t sBa = sb + 10240 + lr * 80 + lc * 16;
    const uint32_t sBb = sBa + 64 * 80;

    const uint32_t aBase = sb + (uint32_t)((warpRow + (lane & 15)) * 80 + (lane >> 4) * 16);
    const uint32_t bBase = sb + 10240 +
        (uint32_t)((warpCol + (lane & 7) + ((lane >> 4) & 1) * 8) * 80 +
                   ((lane >> 3) & 1) * 16);

    float acc[4][4][4];
    #pragma unroll
    for (int i = 0; i < 4; i++)
        #pragma unroll
        for (int j = 0; j < 4; j++)
            #pragma unroll
            for (int r = 0; r < 4; r++) acc[i][j][r] = 0.f;

    const int NKT = D_ / 32;

    #pragma unroll
    for (int s = 0; s < 2; s++) {
        uint32_t so = s * P3_STAGE;
        cp_async16(sAa + so, Aga + s * 32);
        cp_async16(sAb + so, Agb + s * 32);
        cp_async16(sBa + so, Bga + s * 32);
        cp_async16(sBb + so, Bgb + s * 32);
        CP_COMMIT();
    }

    int stage = 0;
    for (int kt = 0; kt < NKT; kt++) {
        if (kt >= NKT - 2) { CP_WAIT(0); } else { CP_WAIT(1); }
        __syncthreads();

        if (kt + 2 < NKT) {
            int ns = (kt + 2) % 3;
            uint32_t so = ns * P3_STAGE;
            int ko = (kt + 2) * 32;
            cp_async16(sAa + so, Aga + ko);
            cp_async16(sAb + so, Agb + ko);
            cp_async16(sBa + so, Bga + ko);
            cp_async16(sBb + so, Bgb + ko);
            CP_COMMIT();
        }

        const uint32_t so = stage * P3_STAGE;
        #pragma unroll
        for (int ks = 0; ks < 2; ks++) {
            uint32_t af[4][4], bp[2][4];
            #pragma unroll
            for (int mt = 0; mt < 4; mt++)
                ldsm_x4(af[mt], aBase + so + mt * (16 * 80) + ks * 32);
            #pragma unroll
            for (int p = 0; p < 2; p++)
                ldsm_x4(bp[p], bBase + so + p * (16 * 80) + ks * 32);
            #pragma unroll
            for (int mt = 0; mt < 4; mt++) {
                #pragma unroll
                for (int p = 0; p < 2; p++) {
                    uint32_t b0[2] = { bp[p][0], bp[p][1] };
                    uint32_t b1[2] = { bp[p][2], bp[p][3] };
                    mma_h(acc[mt][p * 2],     af[mt], b0);
                    mma_h(acc[mt][p * 2 + 1], af[mt], b1);
                }
            }
        }
        stage = (stage + 1) % 3;
        __syncthreads();
    }

    const int g = lane >> 2;
    const int t = lane & 3;
    #pragma unroll
    for (int mt = 0; mt < 4; mt++) {
        int r = rowBase + warpRow + mt * 16 + g;
        #pragma unroll
        for (int nt = 0; nt < 4; nt++) {
            int c = colBase + warpCol + nt * 8 + 2 * t;
            float b0 = bvec[c], b1 = bvec[c + 1];
            uint32_t h0 = pack_h2(fmaxf(acc[mt][nt][0] + b0, 0.f),
                                  fmaxf(acc[mt][nt][1] + b1, 0.f));
            uint32_t h1 = pack_h2(fmaxf(acc[mt][nt][2] + b0, 0.f),
                                  fmaxf(acc[mt][nt][3] + b1, 0.f));
            *(uint32_t*)&C[(size_t)r * D_ + c]       = h0;
            *(uint32_t*)&C[(size_t)(r + 8) * D_ + c] = h1;
        }
    }
}

// ============================================================================
// scores + softmax fused: attn_h[b] = softmax(q_b @ k_b^T * scale + bias)
// ============================================================================
#define S_STAGE_W 5760
#define S_SC_OFF  (2 * S_STAGE_W)
#define SCORES_SMEM (2 * S_STAGE_W * 4 + 144 * 148 * 4)   // 131328 B

__global__ __launch_bounds__(288, 1)
void scores_sm(const __half* __restrict__ q, const __half* __restrict__ k,
               const float* __restrict__ bias, __half* __restrict__ attn_h,
               float scale)
{
    extern __shared__ uint32_t smu[];
    const uint32_t sb = smem_u32p(smu);
    float* Ssc = (float*)(smu + S_SC_OFF);     // [144][148]

    const int b = blockIdx.x;
    const __half* qb = q + (size_t)b * S_ * D_;
    const __half* kb = k + (size_t)b * S_ * D_;

    const int tid  = threadIdx.x;
    const int lane = tid & 31;
    const int warp = tid >> 5;
    const int g = lane >> 2;
    const int t = lane & 3;
    const int warpRow = (warp / 3) * 48;
    const int warpCol = (warp % 3) * 48;

    const int r = tid >> 1;
    const int c0 = tid & 1;
    const __half* qg = qb + (size_t)r * D_;
    const __half* kg = kb + (size_t)r * D_;
    const uint32_t qSb = sb + r * 80;
    const uint32_t kSb = sb + 11520 + r * 80;

    float acc[3][6][4];
    #pragma unroll
    for (int i = 0; i < 3; i++)
        #pragma unroll
        for (int j = 0; j < 6; j++)
            #pragma unroll
            for (int rr = 0; rr < 4; rr++) acc[i][j][rr] = 0.f;

    const int NKT = D_ / 32;

    #pragma unroll
    for (int j = 0; j < 2; j++) {
        int ch = c0 + j * 2;
        cp_async16(qSb + ch * 16, qg + ch * 8);
        cp_async16(kSb + ch * 16, kg + ch * 8);
    }
    CP_COMMIT();

    for (int kt = 0; kt < NKT; kt++) {
        const int cur = kt & 1;
        if (kt + 1 < NKT) {
            const int nxt = cur ^ 1;
            #pragma unroll
            for (int j = 0; j < 2; j++) {
                int ch = c0 + j * 2;
                cp_async16(qSb + nxt * 23040 + ch * 16, qg + (kt + 1) * 32 + ch * 8);
                cp_async16(kSb + nxt * 23040 + ch * 16, kg + (kt + 1) * 32 + ch * 8);
            }
            CP_COMMIT();
            CP_WAIT(1);
        } else {
            CP_WAIT(0);
        }
        __syncthreads();

        const uint32_t* Qc = smu + cur * S_STAGE_W;
        const uint32_t* Kc = smu + cur * S_STAGE_W + 2880;
        #pragma unroll
        for (int ks = 0; ks < 2; ks++) {
            const int kd = ks * 8;
            uint32_t af[3][4], bf[6][2];
            #pragma unroll
            for (int mt = 0; mt < 3; mt++) {
                int m0 = warpRow + mt * 16;
                af[mt][0] = Qc[(m0 + g)     * 20 + kd + t];
                af[mt][1] = Qc[(m0 + g + 8) * 20 + kd + t];
                af[mt][2] = Qc[(m0 + g)     * 20 + kd + t + 4];
                af[mt][3] = Qc[(m0 + g + 8) * 20 + kd + t + 4];
            }
            #pragma unroll
            for (int nt = 0; nt < 6; nt++) {
                int n0 = warpCol + nt * 8;
                bf[nt][0] = Kc[(n0 + g) * 20 + kd + t];
                bf[nt][1] = Kc[(n0 + g) * 20 + kd + t + 4];
            }
            #pragma unroll
            for (int mt = 0; mt < 3; mt++)
                #pragma unroll
                for (int nt = 0; nt < 6; nt++)
                    mma_h(acc[mt][nt], af[mt], bf[nt]);
        }
        __syncthreads();
    }

    // ---- epilogue: scale + bias -> smem score buffer ----
    #pragma unroll
    for (int mt = 0; mt < 3; mt++) {
        int m = warpRow + mt * 16 + g;
        #pragma unroll
        for (int nt = 0; nt < 6; nt++) {
            int n = warpCol + nt * 8 + 2 * t;
            float2 bA = *(const float2*)&bias[m * S_ + n];
            float2 bB = *(const float2*)&bias[(m + 8) * S_ + n];
            Ssc[m * 148 + n]           = fmaf(acc[mt][nt][0], scale, bA.x);
            Ssc[m * 148 + n + 1]       = fmaf(acc[mt][nt][1], scale, bA.y);
            Ssc[(m + 8) * 148 + n]     = fmaf(acc[mt][nt][2], scale, bB.x);
            Ssc[(m + 8) * 148 + n + 1] = fmaf(acc[mt][nt][3], scale, bB.y);
        }
    }
    __syncthreads();

    // ---- softmax: warp per row, 16 rows per warp, emit fp16 ----
    __half* ao = attn_h + (size_t)b * S_ * S_;
    #pragma unroll
    for (int rr = 0; rr < 16; rr++) {
        int m = warp * 16 + rr;
        float v[5];
        float mx = -INFINITY;
        #pragma unroll
        for (int i = 0; i < 5; i++) {
            int idx = lane + i * 32;
            v[i] = (idx < S_) ? Ssc[m * 148 + idx] : -INFINITY;
            mx = fmaxf(mx, v[i]);
        }
        #pragma unroll
        for (int o = 16; o; o >>= 1) mx = fmaxf(mx, __shfl_xor_sync(0xffffffffu, mx, o));
        float s = 0.f;
        #pragma unroll
        for (int i = 0; i < 5; i++) {
            v[i] = __expf(v[i] - mx);
            s += v[i];
        }
        #pragma unroll
        for (int o = 16; o; o >>= 1) s += __shfl_xor_sync(0xffffffffu, s, o);
        float inv = 1.f / s;
        #pragma unroll
        for (int i = 0; i < 5; i++) {
            int idx = lane + i * 32;
            if (idx < S_) ao[m * S_ + idx] = __float2half(v[i] * inv);
        }
    }
}

// ============================================================================
// out = attn_h @ v  -- fp16 mma, attn already fp16 in global
// ============================================================================
#define AV_SMEM ((144 * 28 + 128 * 28) * 4)

__global__ __launch_bounds__(384, 1)
void av_h2(const __half* __restrict__ attn_h, const __half* __restrict__ v,
           float* __restrict__ out)
{
    extern __shared__ uint32_t smu[];
    uint32_t* An = smu;
    uint32_t* Vs = smu + 144 * 28;

    const int b = blockIdx.y;
    const int colBase = blockIdx.x * 128;
    const __half* ab = attn_h + (size_t)b * S_ * S_;
    const __half* vb = v + (size_t)b * S_ * D_;

    const int tid  = threadIdx.x;
    const int lane = tid & 31;
    const int warp = tid >> 5;
    const int g = lane >> 2;
    const int t = lane & 3;
    const int warpRow = (warp >> 2) * 48;
    const int warpCol = (warp & 3) * 32;

    float acc[3][4][4];
    #pragma unroll
    for (int i = 0; i < 3; i++)
        #pragma unroll
        for (int j = 0; j < 4; j++)
            #pragma unroll
            for (int r = 0; r < 4; r++) acc[i][j][r] = 0.f;

    for (int k0 = 0; k0 < S_; k0 += 48) {
        // attn tile (144 x 48 halves) from global: 6 uint4 per row
        for (int idx = tid; idx < 144 * 6; idx += 384) {
            int rr = idx / 6, cc = idx % 6;
            uint4 u = *(const uint4*)&ab[rr * S_ + k0 + cc * 8];
            *(uint4*)&An[rr * 28 + cc * 4] = u;
        }
        // v tile (48 tokens x 128 d) -> transposed smem [d][token]
        unsigned short* vs16 = (unsigned short*)Vs;
        #pragma unroll
        for (int j = 0; j < 2; j++) {
            int idx = tid + j * 384;
            int tk = idx >> 4;
            int dch = idx & 15;
            uint4 u = *(const uint4*)&vb[(size_t)(k0 + tk) * D_ + colBase + dch * 8];
            const unsigned short* hs = (const unsigned short*)&u;
            #pragma unroll
            for (int e = 0; e < 8; e++)
                vs16[(dch * 8 + e) * 56 + tk] = hs[e];
        }
        __syncthreads();

        #pragma unroll
        for (int ks = 0; ks < 3; ks++) {
            const int kd = ks * 8;
            uint32_t af[3][4], bf[4][2];
            #pragma unroll
            for (int mt = 0; mt < 3; mt++) {
                int m0 = warpRow + mt * 16;
                af[mt][0] = An[(m0 + g)     * 28 + kd + t];
                af[mt][1] = An[(m0 + g + 8) * 28 + kd + t];
                af[mt][2] = An[(m0 + g)     * 28 + kd + t + 4];
                af[mt][3] = An[(m0 + g + 8) * 28 + kd + t + 4];
            }
            #pragma unroll
            for (int nt = 0; nt < 4; nt++) {
                int n0 = warpCol + nt * 8;
                bf[nt][0] = Vs[(n0 + g) * 28 + kd + t];
                bf[nt][1] = Vs[(n0 + g) * 28 + kd + t + 4];
            }
            #pragma unroll
            for (int mt = 0; mt < 3; mt++)
                #pragma unroll
                for (int nt = 0; nt < 4; nt++)
                    mma_h(acc[mt][nt], af[mt], bf[nt]);
        }
        __syncthreads();
    }

    #pragma unroll
    for (int mt = 0; mt < 3; mt++) {
        int m = warpRow + mt * 16 + g;
        #pragma unroll
        for (int nt = 0; nt < 4; nt++) {
            int n = colBase + warpCol + nt * 8 + 2 * t;
            float2 o0 = { acc[mt][nt][0], acc[mt][nt][1] };
            float2 o1 = { acc[mt][nt][2], acc[mt][nt][3] };
            *(float2*)&out[((size_t)b * S_ + m) * D_ + n]     = o0;
            *(float2*)&out[((size_t)b * S_ + m + 8) * D_ + n] = o1;
        }
    }
}

// ============================================================================
// launch
// ============================================================================
extern "C" void kernel_launch(void* const* d_in, const int* in_sizes, int n_in,
                              void* d_out, int out_size)
{
    const float* query = (const float*)d_in[0];
    const float* key   = (const float*)d_in[1];
    const float* value = (const float*)d_in[2];
    const float* Wq    = (const float*)d_in[3];
    const float* bq    = (const float*)d_in[4];
    const float* Wk    = (const float*)d_in[5];
    const float* bk    = (const float*)d_in[6];
    const float* Wv    = (const float*)d_in[7];
    const float* bv    = (const float*)d_in[8];
    const float* Wl    = (const float*)d_in[9];
    const float* bl    = (const float*)d_in[10];
    const float* wg    = (const float*)d_in[11];
    float* out = (float*)d_out;

    __half* ah;   cudaGetSymbolAddress((void**)&ah,   g_ah);
    __half* qh;   cudaGetSymbolAddress((void**)&qh,   g_q);
    __half* kh;   cudaGetSymbolAddress((void**)&kh,   g_k);
    __half* vh;   cudaGetSymbolAddress((void**)&vh,   g_v);
    __half* wt;   cudaGetSymbolAddress((void**)&wt,   g_wt);
    __half* athh; cudaGetSymbolAddress((void**)&athh, g_attn_h);
    float* bias;  cudaGetSymbolAddress((void**)&bias, g_bias);
    float* R;     cudaGetSymbolAddress((void**)&R,    g_R);

    cudaFuncSetAttribute(proj_h2,
                         cudaFuncAttributeMaxDynamicSharedMemorySize, PROJ_SMEM);
    cudaFuncSetAttribute(scores_sm,
                         cudaFuncAttributeMaxDynamicSharedMemorySize, SCORES_SMEM);
    cudaFuncSetAttribute(av_h2,
                         cudaFuncAttributeMaxDynamicSharedMemorySize, AV_SMEM);

    // 1. fused setup: input cvt + weight transpose + rel table
    setup_fused<<<SETUP_BLOCKS, 256>>>(query, key, value, ah,
                                       Wq, Wk, Wv, wt, Wl, bl, R);

    // 2. bias table (tgemm + scatter fused)
    tgemm_bias<<<dim3(144, 4), 256>>>(wg, R, bias);

    // 3. projections (fp16 HMMA)
    proj_h2<<<dim3(8, 144, 3), 256, PROJ_SMEM>>>(ah, wt, bq, bk, bv, qh, kh, vh);

    // 4. scores + softmax fused -> fp16 attn
    float scale = 1.0f / sqrtf((float)D_);
    scores_sm<<<B_, 288, SCORES_SMEM>>>(qh, kh, bias, athh, scale);

    // 5. out = attn @ v
    av_h2<<<dim3(D_ / 128, B_), 384, AV_SMEM>>>(athh, vh, out);
}

// round 10
// speedup vs baseline: 6.0435x; 1.0218x over previous
#include <cuda_runtime.h>
#include <cuda_fp16.h>
#include <math.h>
#include <stdint.h>

// ============================================================================
// RegionAugmentedSelfAttention  (B=128, S=144, D=1024, GRID=12)
//   R10: scores split into 48-row tiles (grid 3x128, 3 warps, 4 CTA/SM),
//        softmax in registers (no smem score buffer). Rest = R9.
// ============================================================================

#define B_  128
#define S_  144
#define D_  1024
#define BS_ (B_ * S_)          // 18432

// -------- scratch (static device globals) -----------------------------------
__device__ __align__(16) unsigned short g_ah[3 * BS_ * D_];  // half q/k/v inputs
__device__ __align__(16) unsigned short g_q[BS_ * D_];
__device__ __align__(16) unsigned short g_k[BS_ * D_];
__device__ __align__(16) unsigned short g_v[BS_ * D_];
__device__ __align__(16) unsigned short g_wt[3 * D_ * D_];   // half W^T (n,k)
__device__ __align__(16) unsigned short g_attn_h[B_ * S_ * S_]; // half attn
__device__ float g_bias[S_ * S_];
__device__ float g_R[144 * D_];

// ---------------------------------------------------------------------------
// helpers
// ---------------------------------------------------------------------------
__device__ __forceinline__ uint32_t pack_h2(float lo, float hi) {
    uint32_t r;
    asm("cvt.rn.f16x2.f32 %0, %1, %2;" : "=r"(r) : "f"(hi), "f"(lo));
    return r;
}

__device__ __forceinline__ void mma_h(float (&d)[4],
                                      const uint32_t (&a)[4],
                                      const uint32_t (&b)[2]) {
    asm volatile(
        "mma.sync.aligned.m16n8k16.row.col.f32.f16.f16.f32 "
        "{%0,%1,%2,%3}, {%4,%5,%6,%7}, {%8,%9}, {%0,%1,%2,%3};\n"
        : "+f"(d[0]), "+f"(d[1]), "+f"(d[2]), "+f"(d[3])
        : "r"(a[0]), "r"(a[1]), "r"(a[2]), "r"(a[3]),
          "r"(b[0]), "r"(b[1]));
}

__device__ __forceinline__ void ldsm_x4(uint32_t (&r)[4], uint32_t addr) {
    asm volatile("ldmatrix.sync.aligned.m8n8.x4.shared.b16 {%0,%1,%2,%3}, [%4];"
                 : "=r"(r[0]), "=r"(r[1]), "=r"(r[2]), "=r"(r[3]) : "r"(addr));
}

__device__ __forceinline__ void cp_async16(uint32_t smem_addr, const void* gptr) {
    asm volatile("cp.async.cg.shared.global [%0], [%1], 16;\n"
                 :: "r"(smem_addr), "l"(gptr));
}
#define CP_COMMIT()  asm volatile("cp.async.commit_group;\n")
#define CP_WAIT(N)   asm volatile("cp.async.wait_group %0;\n" :: "n"(N))

__device__ __forceinline__ uint32_t smem_u32p(const void* p) {
    return (uint32_t)__cvta_generic_to_shared(p);
}

// ============================================================================
// Fused setup: blocks [0,27648) a2h | [27648,30720) transpose_w |
//              [30720,30864) rel
// ============================================================================
#define SETUP_A2H_BLOCKS   27648      // 3*BS_*D_/8/256
#define SETUP_TRANS_BLOCKS 3072       // 3 * 32 * 32
#define SETUP_REL_BLOCKS   144
#define SETUP_BLOCKS (SETUP_A2H_BLOCKS + SETUP_TRANS_BLOCKS + SETUP_REL_BLOCKS)

__global__ __launch_bounds__(256)
void setup_fused(const float* __restrict__ q, const float* __restrict__ k,
                 const float* __restrict__ v, __half* __restrict__ ah,
                 const float* __restrict__ Wq, const float* __restrict__ Wk,
                 const float* __restrict__ Wv, __half* __restrict__ Wt,
                 const float* __restrict__ Wl, const float* __restrict__ bl,
                 float* __restrict__ R)
{
    __shared__ float t[32][33];
    const int bid = blockIdx.x;
    const int tid = threadIdx.x;

    if (bid < SETUP_A2H_BLOCKS) {
        const size_t per = (size_t)BS_ * D_ / 8;
        size_t i = (size_t)bid * 256 + tid;
        const float* src;
        size_t off;
        if (i < per)           { src = q; off = i; }
        else if (i < 2 * per)  { src = k; off = i - per; }
        else                   { src = v; off = i - 2 * per; }
        float4 x0 = ((const float4*)src)[off * 2];
        float4 x1 = ((const float4*)src)[off * 2 + 1];
        uint4 u = { pack_h2(x0.x, x0.y), pack_h2(x0.z, x0.w),
                    pack_h2(x1.x, x1.y), pack_h2(x1.z, x1.w) };
        ((uint4*)ah)[i] = u;
    } else if (bid < SETUP_A2H_BLOCKS + SETUP_TRANS_BLOCKS) {
        int b2 = bid - SETUP_A2H_BLOCKS;
        int z = b2 >> 10;
        int rem = b2 & 1023;
        int bx = rem & 31, by = rem >> 5;
        const float* W = (z == 0) ? Wq : (z == 1) ? Wk : Wv;
        __half* O = Wt + (size_t)z * D_ * D_;
        int x0 = bx * 32, y0 = by * 32;
        int tx = tid & 31, ty = tid >> 5;
        #pragma unroll
        for (int r = ty; r < 32; r += 8)
            t[r][tx] = W[(size_t)(y0 + r) * D_ + x0 + tx];
        __syncthreads();
        #pragma unroll
        for (int r = ty; r < 32; r += 8)
            O[(size_t)(x0 + r) * D_ + y0 + tx] = __float2half(t[tx][r]);
    } else {
        int c = bid - (SETUP_A2H_BLOCKS + SETUP_TRANS_BLOCKS);
        int a = c / 12, b = c % 12;
        float dx = logf(fmaxf((float)a * 0.5f, 1e-10f));
        float dy = logf(fmaxf((float)b * 0.5f, 1e-10f));
        for (int d = tid; d < D_; d += 256)
            R[c * D_ + d] = fmaxf(fmaf(dx, Wl[d], fmaf(dy, Wl[D_ + d], bl[d])), 0.f);
    }
}

// ============================================================================
// tgemm + bias scatter fused.  grid (144 rows, 4 quarters).
// ============================================================================
__global__ __launch_bounds__(256)
void tgemm_bias(const float* __restrict__ wg, const float* __restrict__ R,
                float* __restrict__ bias)
{
    __shared__ float w[D_];
    __shared__ float Tp[36];
    const int i = blockIdx.x;
    const int qt = blockIdx.y;
    const int tid = threadIdx.x;

    *(float4*)&w[tid * 4] = *(const float4*)&wg[(size_t)i * D_ + tid * 4];
    __syncthreads();

    const int warp = tid >> 5;
    const int lane = tid & 31;
    for (int cl = warp; cl < 36; cl += 8) {
        const float* Rc = R + (size_t)(qt * 36 + cl) * D_;
        float s = 0.f;
        #pragma unroll
        for (int d = lane * 4; d < D_; d += 128) {
            float4 r4 = *(const float4*)&Rc[d];
            s += r4.x * w[d] + r4.y * w[d + 1] + r4.z * w[d + 2] + r4.w * w[d + 3];
        }
        #pragma unroll
        for (int o = 16; o; o >>= 1) s += __shfl_xor_sync(0xffffffffu, s, o);
        if (lane == 0) Tp[cl] = s;
    }
    __syncthreads();

    const int base = qt * 36;
    for (int j = tid; j < S_; j += 256) {
        int dr = abs(i / 12 - j / 12);
        int dc = abs(i % 12 - j % 12);
        int combo = dr * 12 + dc;
        if (combo >= base && combo < base + 36)
            bias[i * S_ + j] = fmaxf(Tp[combo - base], 0.f);
    }
}

// ============================================================================
// Projection GEMM  C = relu(A @ W + b)  -- fp16 HMMA (unchanged)
// ============================================================================
#define P3_STAGE 20480
#define PROJ_SMEM (3 * P3_STAGE)        // 61440 B

__global__ __launch_bounds__(256, 2)
void proj_h2(const __half* __restrict__ Ah, const __half* __restrict__ Wt,
             const float* __restrict__ bq, const float* __restrict__ bk,
             const float* __restrict__ bv,
             __half* __restrict__ Cq, __half* __restrict__ Ck,
             __half* __restrict__ Cv)
{
    extern __shared__ char smc[];
    const uint32_t sb = smem_u32p(smc);

    const int z = blockIdx.z;
    const __half* A  = Ah + (size_t)z * BS_ * D_;
    const __half* Bt = Wt + (size_t)z * D_ * D_;
    const float* bvec = (z == 0) ? bq : (z == 1) ? bk : bv;
    __half* C = (z == 0) ? Cq : (z == 1) ? Ck : Cv;

    const int tid  = threadIdx.x;
    const int lane = tid & 31;
    const int warp = tid >> 5;
    const int rowBase = blockIdx.y * 128;
    const int colBase = blockIdx.x * 128;
    const int warpRow = (warp >> 2) * 64;
    const int warpCol = (warp & 3) * 32;

    const int lr = tid >> 2;
    const int lc = tid & 3;
    const __half* Aga = A  + (size_t)(rowBase + lr) * D_ + lc * 8;
    const __half* Agb = A  + (size_t)(rowBase + lr + 64) * D_ + lc * 8;
    const __half* Bga = Bt + (size_t)(colBase + lr) * D_ + lc * 8;
    const __half* Bgb = Bt + (size_t)(colBase + lr + 64) * D_ + lc * 8;
    const uint32_t sAa = sb + lr * 80 + lc * 16;
    const uint32_t sAb = sAa + 64 * 80;
    const uint32_t sBa = sb + 10240 + lr * 80 + lc * 16;
    const uint32_t sBb = sBa + 64 * 80;

    const uint32_t aBase = sb + (uint32_t)((warpRow + (lane & 15)) * 80 + (lane >> 4) * 16);
    const uint32_t bBase = sb + 10240 +
        (uint32_t)((warpCol + (lane & 7) + ((lane >> 4) & 1) * 8) * 80 +
                   ((lane >> 3) & 1) * 16);

    float acc[4][4][4];
    #pragma unroll
    for (int i = 0; i < 4; i++)
        #pragma unroll
        for (int j = 0; j < 4; j++)
            #pragma unroll
            for (int r = 0; r < 4; r++) acc[i][j][r] = 0.f;

    const int NKT = D_ / 32;

    #pragma unroll
    for (int s = 0; s < 2; s++) {
        uint32_t so = s * P3_STAGE;
        cp_async16(sAa + so, Aga + s * 32);
        cp_async16(sAb + so, Agb + s * 32);
        cp_async16(sBa + so, Bga + s * 32);
        cp_async16(sBb + so, Bgb + s * 32);
        CP_COMMIT();
    }

    int stage = 0;
    for (int kt = 0; kt < NKT; kt++) {
        if (kt >= NKT - 2) { CP_WAIT(0); } else { CP_WAIT(1); }
        __syncthreads();

        if (kt + 2 < NKT) {
            int ns = (kt + 2) % 3;
            uint32_t so = ns * P3_STAGE;
            int ko = (kt + 2) * 32;
            cp_async16(sAa + so, Aga + ko);
            cp_async16(sAb + so, Agb + ko);
            cp_async16(sBa + so, Bga + ko);
            cp_async16(sBb + so, Bgb + ko);
            CP_COMMIT();
        }

        const uint32_t so = stage * P3_STAGE;
        #pragma unroll
        for (int ks = 0; ks < 2; ks++) {
            uint32_t af[4][4], bp[2][4];
            #pragma unroll
            for (int mt = 0; mt < 4; mt++)
                ldsm_x4(af[mt], aBase + so + mt * (16 * 80) + ks * 32);
            #pragma unroll
            for (int p = 0; p < 2; p++)
                ldsm_x4(bp[p], bBase + so + p * (16 * 80) + ks * 32);
            #pragma unroll
            for (int mt = 0; mt < 4; mt++) {
                #pragma unroll
                for (int p = 0; p < 2; p++) {
                    uint32_t b0[2] = { bp[p][0], bp[p][1] };
                    uint32_t b1[2] = { bp[p][2], bp[p][3] };
                    mma_h(acc[mt][p * 2],     af[mt], b0);
                    mma_h(acc[mt][p * 2 + 1], af[mt], b1);
                }
            }
        }
        stage = (stage + 1) % 3;
        __syncthreads();
    }

    const int g = lane >> 2;
    const int t = lane & 3;
    #pragma unroll
    for (int mt = 0; mt < 4; mt++) {
        int r = rowBase + warpRow + mt * 16 + g;
        #pragma unroll
        for (int nt = 0; nt < 4; nt++) {
            int c = colBase + warpCol + nt * 8 + 2 * t;
            float b0 = bvec[c], b1 = bvec[c + 1];
            uint32_t h0 = pack_h2(fmaxf(acc[mt][nt][0] + b0, 0.f),
                                  fmaxf(acc[mt][nt][1] + b1, 0.f));
            uint32_t h1 = pack_h2(fmaxf(acc[mt][nt][2] + b0, 0.f),
                                  fmaxf(acc[mt][nt][3] + b1, 0.f));
            *(uint32_t*)&C[(size_t)r * D_ + c]       = h0;
            *(uint32_t*)&C[(size_t)(r + 8) * D_ + c] = h1;
        }
    }
}

// ============================================================================
// scores + softmax, register-resident: grid (3 row-tiles, 128 batches),
//   3 warps (48x48 each), 2-stage cp.async over D, softmax via quad-shuffle
//   + 1.5KB cross-warp partials. Emits fp16 attn.
//   smem: 2 stages x (192 rows x 80B) + partials = 32256 B -> ~4 CTA/SM.
// ============================================================================
#define S3_STAGE 15360
#define S3_PART  (2 * S3_STAGE)
#define SCORES_SMEM3 (S3_PART + 48 * 4 * 4 * 2)   // 32256 B

__global__ __launch_bounds__(96)
void scores_reg(const __half* __restrict__ q, const __half* __restrict__ k,
                const float* __restrict__ bias, __half* __restrict__ attn_h,
                float scale)
{
    extern __shared__ char smc[];
    const uint32_t sb = smem_u32p(smc);
    float* pmax = (float*)(smc + S3_PART);         // [48][4]
    float* psum = pmax + 48 * 4;                   // [48][4]

    const int b = blockIdx.y;
    const int rowBase = blockIdx.x * 48;
    const __half* qb = q + (size_t)b * S_ * D_;
    const __half* kb = k + (size_t)b * S_ * D_;

    const int tid  = threadIdx.x;
    const int lane = tid & 31;
    const int warp = tid >> 5;                     // 0..2
    const int g = lane >> 2;
    const int t = lane & 3;
    const int warpCol = warp * 48;

    // loader: thread covers rows (tid>>2)+24j (j=0..7; j<2 q-rows, j>=2 k-rows)
    const int lr = tid >> 2;                       // 0..23
    const int lc = tid & 3;                        // 0..3
    const __half* qg = qb + (size_t)(rowBase + lr) * D_ + lc * 8;
    const __half* kg = kb + (size_t)lr * D_ + lc * 8;
    const uint32_t sL = sb + lr * 80 + lc * 16;

    // ldmatrix bases (q at smem rows 0..47, k at rows 48..191)
    const uint32_t aBase = sb + (uint32_t)((lane & 15) * 80 + (lane >> 4) * 16);
    const uint32_t bBase = sb + 48 * 80 +
        (uint32_t)((warpCol + (lane & 7) + ((lane >> 4) & 1) * 8) * 80 +
                   ((lane >> 3) & 1) * 16);

    float acc[3][6][4];
    #pragma unroll
    for (int i = 0; i < 3; i++)
        #pragma unroll
        for (int j = 0; j < 6; j++)
            #pragma unroll
            for (int r = 0; r < 4; r++) acc[i][j][r] = 0.f;

    const int NKT = D_ / 32;

    // prologue: stage 0
    #pragma unroll
    for (int j = 0; j < 2; j++)
        cp_async16(sL + j * (24 * 80), qg + (size_t)j * 24 * D_);
    #pragma unroll
    for (int j = 0; j < 6; j++)
        cp_async16(sL + (j + 2) * (24 * 80), kg + (size_t)j * 24 * D_);
    CP_COMMIT();

    for (int kt = 0; kt < NKT; kt++) {
        const int cur = kt & 1;
        if (kt + 1 < NKT) {
            const int nxt = cur ^ 1;
            const int ko = (kt + 1) * 32;
            #pragma unroll
            for (int j = 0; j < 2; j++)
                cp_async16(sL + nxt * S3_STAGE + j * (24 * 80),
                           qg + (size_t)j * 24 * D_ + ko);
            #pragma unroll
            for (int j = 0; j < 6; j++)
                cp_async16(sL + nxt * S3_STAGE + (j + 2) * (24 * 80),
                           kg + (size_t)j * 24 * D_ + ko);
            CP_COMMIT();
            CP_WAIT(1);
        } else {
            CP_WAIT(0);
        }
        __syncthreads();

        const uint32_t so = cur * S3_STAGE;
        #pragma unroll
        for (int ks = 0; ks < 2; ks++) {
            uint32_t af[3][4], bp[3][4];
            #pragma unroll
            for (int mt = 0; mt < 3; mt++)
                ldsm_x4(af[mt], aBase + so + mt * (16 * 80) + ks * 32);
            #pragma unroll
            for (int p = 0; p < 3; p++)
                ldsm_x4(bp[p], bBase + so + p * (16 * 80) + ks * 32);
            #pragma unroll
            for (int mt = 0; mt < 3; mt++) {
                #pragma unroll
                for (int p = 0; p < 3; p++) {
                    uint32_t b0[2] = { bp[p][0], bp[p][1] };
                    uint32_t b1[2] = { bp[p][2], bp[p][3] };
                    mma_h(acc[mt][p * 2],     af[mt], b0);
                    mma_h(acc[mt][p * 2 + 1], af[mt], b1);
                }
            }
        }
        __syncthreads();
    }

    // ---- scale + bias into acc ----
    #pragma unroll
    for (int mt = 0; mt < 3; mt++) {
        int m = rowBase + mt * 16 + g;
        #pragma unroll
        for (int nt = 0; nt < 6; nt++) {
            int n = warpCol + nt * 8 + 2 * t;
            float2 bA = *(const float2*)&bias[m * S_ + n];
            float2 bB = *(const float2*)&bias[(m + 8) * S_ + n];
            acc[mt][nt][0] = fmaf(acc[mt][nt][0], scale, bA.x);
            acc[mt][nt][1] = fmaf(acc[mt][nt][1], scale, bA.y);
            acc[mt][nt][2] = fmaf(acc[mt][nt][2], scale, bB.x);
            acc[mt][nt][3] = fmaf(acc[mt][nt][3], scale, bB.y);
        }
    }

    // ---- row max: per-thread over 12 cols, quad-shuffle, cross-warp smem ----
    float mx0[3], mx1[3];
    #pragma unroll
    for (int mt = 0; mt < 3; mt++) {
        float a0 = -INFINITY, a1 = -INFINITY;
        #pragma unroll
        for (int nt = 0; nt < 6; nt++) {
            a0 = fmaxf(a0, fmaxf(acc[mt][nt][0], acc[mt][nt][1]));
            a1 = fmaxf(a1, fmaxf(acc[mt][nt][2], acc[mt][nt][3]));
        }
        #pragma unroll
        for (int o = 1; o < 4; o <<= 1) {
            a0 = fmaxf(a0, __shfl_xor_sync(0xffffffffu, a0, o));
            a1 = fmaxf(a1, __shfl_xor_sync(0xffffffffu, a1, o));
        }
        mx0[mt] = a0; mx1[mt] = a1;
        if (t == 0) {
            pmax[(mt * 16 + g) * 4 + warp]     = a0;
            pmax[(mt * 16 + g + 8) * 4 + warp] = a1;
        }
    }
    __syncthreads();
    #pragma unroll
    for (int mt = 0; mt < 3; mt++) {
        int r0 = (mt * 16 + g) * 4, r1 = (mt * 16 + g + 8) * 4;
        mx0[mt] = fmaxf(fmaxf(pmax[r0], pmax[r0 + 1]), pmax[r0 + 2]);
        mx1[mt] = fmaxf(fmaxf(pmax[r1], pmax[r1 + 1]), pmax[r1 + 2]);
    }

    // ---- exp (in place) + row sum ----
    float s0[3], s1[3];
    #pragma unroll
    for (int mt = 0; mt < 3; mt++) {
        float a0 = 0.f, a1 = 0.f;
        #pragma unroll
        for (int nt = 0; nt < 6; nt++) {
            acc[mt][nt][0] = __expf(acc[mt][nt][0] - mx0[mt]);
            acc[mt][nt][1] = __expf(acc[mt][nt][1] - mx0[mt]);
            acc[mt][nt][2] = __expf(acc[mt][nt][2] - mx1[mt]);
            acc[mt][nt][3] = __expf(acc[mt][nt][3] - mx1[mt]);
            a0 += acc[mt][nt][0] + acc[mt][nt][1];
            a1 += acc[mt][nt][2] + acc[mt][nt][3];
        }
        #pragma unroll
        for (int o = 1; o < 4; o <<= 1) {
            a0 += __shfl_xor_sync(0xffffffffu, a0, o);
            a1 += __shfl_xor_sync(0xffffffffu, a1, o);
        }
        s0[mt] = a0; s1[mt] = a1;
        if (t == 0) {
            psum[(mt * 16 + g) * 4 + warp]     = a0;
            psum[(mt * 16 + g + 8) * 4 + warp] = a1;
        }
    }
    __syncthreads();

    // ---- normalize + fp16 store ----
    __half* ao = attn_h + (size_t)b * S_ * S_;
    #pragma unroll
    for (int mt = 0; mt < 3; mt++) {
        int r0 = (mt * 16 + g) * 4, r1 = (mt * 16 + g + 8) * 4;
        float i0 = 1.f / (psum[r0] + psum[r0 + 1] + psum[r0 + 2]);
        float i1 = 1.f / (psum[r1] + psum[r1 + 1] + psum[r1 + 2]);
        int m = rowBase + mt * 16 + g;
        #pragma unroll
        for (int nt = 0; nt < 6; nt++) {
            int n = warpCol + nt * 8 + 2 * t;
            *(uint32_t*)&ao[(size_t)m * S_ + n] =
                pack_h2(acc[mt][nt][0] * i0, acc[mt][nt][1] * i0);
            *(uint32_t*)&ao[(size_t)(m + 8) * S_ + n] =
                pack_h2(acc[mt][nt][2] * i1, acc[mt][nt][3] * i1);
        }
    }
}

// ============================================================================
// out = attn_h @ v  -- fp16 mma (unchanged from R9)
// ============================================================================
#define AV_SMEM ((144 * 28 + 128 * 28) * 4)

__global__ __launch_bounds__(384, 1)
void av_h2(const __half* __restrict__ attn_h, const __half* __restrict__ v,
           float* __restrict__ out)
{
    extern __shared__ uint32_t smu[];
    uint32_t* An = smu;
    uint32_t* Vs = smu + 144 * 28;

    const int b = blockIdx.y;
    const int colBase = blockIdx.x * 128;
    const __half* ab = attn_h + (size_t)b * S_ * S_;
    const __half* vb = v + (size_t)b * S_ * D_;

    const int tid  = threadIdx.x;
    const int lane = tid & 31;
    const int warp = tid >> 5;
    const int g = lane >> 2;
    const int t = lane & 3;
    const int warpRow = (warp >> 2) * 48;
    const int warpCol = (warp & 3) * 32;

    float acc[3][4][4];
    #pragma unroll
    for (int i = 0; i < 3; i++)
        #pragma unroll
        for (int j = 0; j < 4; j++)
            #pragma unroll
            for (int r = 0; r < 4; r++) acc[i][j][r] = 0.f;

    for (int k0 = 0; k0 < S_; k0 += 48) {
        for (int idx = tid; idx < 144 * 6; idx += 384) {
            int rr = idx / 6, cc = idx % 6;
            uint4 u = *(const uint4*)&ab[rr * S_ + k0 + cc * 8];
            *(uint4*)&An[rr * 28 + cc * 4] = u;
        }
        unsigned short* vs16 = (unsigned short*)Vs;
        #pragma unroll
        for (int j = 0; j < 2; j++) {
            int idx = tid + j * 384;
            int tk = idx >> 4;
            int dch = idx & 15;
            uint4 u = *(const uint4*)&vb[(size_t)(k0 + tk) * D_ + colBase + dch * 8];
            const unsigned short* hs = (const unsigned short*)&u;
            #pragma unroll
            for (int e = 0; e < 8; e++)
                vs16[(dch * 8 + e) * 56 + tk] = hs[e];
        }
        __syncthreads();

        #pragma unroll
        for (int ks = 0; ks < 3; ks++) {
            const int kd = ks * 8;
            uint32_t af[3][4], bf[4][2];
            #pragma unroll
            for (int mt = 0; mt < 3; mt++) {
                int m0 = warpRow + mt * 16;
                af[mt][0] = An[(m0 + g)     * 28 + kd + t];
                af[mt][1] = An[(m0 + g + 8) * 28 + kd + t];
                af[mt][2] = An[(m0 + g)     * 28 + kd + t + 4];
                af[mt][3] = An[(m0 + g + 8) * 28 + kd + t + 4];
            }
            #pragma unroll
            for (int nt = 0; nt < 4; nt++) {
                int n0 = warpCol + nt * 8;
                bf[nt][0] = Vs[(n0 + g) * 28 + kd + t];
                bf[nt][1] = Vs[(n0 + g) * 28 + kd + t + 4];
            }
            #pragma unroll
            for (int mt = 0; mt < 3; mt++)
                #pragma unroll
                for (int nt = 0; nt < 4; nt++)
                    mma_h(acc[mt][nt], af[mt], bf[nt]);
        }
        __syncthreads();
    }

    #pragma unroll
    for (int mt = 0; mt < 3; mt++) {
        int m = warpRow + mt * 16 + g;
        #pragma unroll
        for (int nt = 0; nt < 4; nt++) {
            int n = colBase + warpCol + nt * 8 + 2 * t;
            float2 o0 = { acc[mt][nt][0], acc[mt][nt][1] };
            float2 o1 = { acc[mt][nt][2], acc[mt][nt][3] };
            *(float2*)&out[((size_t)b * S_ + m) * D_ + n]     = o0;
            *(float2*)&out[((size_t)b * S_ + m + 8) * D_ + n] = o1;
        }
    }
}

// ============================================================================
// launch
// ============================================================================
extern "C" void kernel_launch(void* const* d_in, const int* in_sizes, int n_in,
                              void* d_out, int out_size)
{
    const float* query = (const float*)d_in[0];
    const float* key   = (const float*)d_in[1];
    const float* value = (const float*)d_in[2];
    const float* Wq    = (const float*)d_in[3];
    const float* bq    = (const float*)d_in[4];
    const float* Wk    = (const float*)d_in[5];
    const float* bk    = (const float*)d_in[6];
    const float* Wv    = (const float*)d_in[7];
    const float* bv    = (const float*)d_in[8];
    const float* Wl    = (const float*)d_in[9];
    const float* bl    = (const float*)d_in[10];
    const float* wg    = (const float*)d_in[11];
    float* out = (float*)d_out;

    __half* ah;   cudaGetSymbolAddress((void**)&ah,   g_ah);
    __half* qh;   cudaGetSymbolAddress((void**)&qh,   g_q);
    __half* kh;   cudaGetSymbolAddress((void**)&kh,   g_k);
    __half* vh;   cudaGetSymbolAddress((void**)&vh,   g_v);
    __half* wt;   cudaGetSymbolAddress((void**)&wt,   g_wt);
    __half* athh; cudaGetSymbolAddress((void**)&athh, g_attn_h);
    float* bias;  cudaGetSymbolAddress((void**)&bias, g_bias);
    float* R;     cudaGetSymbolAddress((void**)&R,    g_R);

    cudaFuncSetAttribute(proj_h2,
                         cudaFuncAttributeMaxDynamicSharedMemorySize, PROJ_SMEM);
    cudaFuncSetAttribute(scores_reg,
                         cudaFuncAttributeMaxDynamicSharedMemorySize, SCORES_SMEM3);
    cudaFuncSetAttribute(av_h2,
                         cudaFuncAttributeMaxDynamicSharedMemorySize, AV_SMEM);

    // 1. fused setup: input cvt + weight transpose + rel table
    setup_fused<<<SETUP_BLOCKS, 256>>>(query, key, value, ah,
                                       Wq, Wk, Wv, wt, Wl, bl, R);

    // 2. bias table (tgemm + scatter fused)
    tgemm_bias<<<dim3(144, 4), 256>>>(wg, R, bias);

    // 3. projections (fp16 HMMA)
    proj_h2<<<dim3(8, 144, 3), 256, PROJ_SMEM>>>(ah, wt, bq, bk, bv, qh, kh, vh);

    // 4. scores + softmax (register-resident) -> fp16 attn
    float scale = 1.0f / sqrtf((float)D_);
    scores_reg<<<dim3(3, B_), 96, SCORES_SMEM3>>>(qh, kh, bias, athh, scale);

    // 5. out = attn @ v
    av_h2<<<dim3(D_ / 128, B_), 384, AV_SMEM>>>(athh, vh, out);
}